// round 4
// baseline (speedup 1.0000x reference)
#include <cuda_runtime.h>
#include <math.h>

// Problem constants
constexpr int BN = 4;
constexpr int NF = 64;
constexpr int H  = 128;
constexpr int W  = 128;
constexpr int HW = H * W;
constexpr int K  = 9;

// Scratch (device globals: no runtime allocation allowed)
__device__ float g_bufA[BN * NF * HW];
__device__ float g_bufB[BN * NF * HW];
__device__ float g_w1T[64 * 128 * 9];        // conv1 weights [cog][ci][tap][o16]
__device__ float g_w2T[64 * 64 * 9];
__device__ float g_w3T[64 * 64 * 9];
__device__ float g_wdT[NF * NF * 9];         // DCN weights [cc][l][o]

__device__ __forceinline__ float lrelu(float v) { return v >= 0.f ? v : 0.1f * v; }

// ---- packed f32x2 helpers (sm_103a FFMA2 path) ------------------------------
using u64 = unsigned long long;

__device__ __forceinline__ u64 pack2(float lo, float hi) {
    u64 r;
    asm("mov.b64 %0, {%1, %2};" : "=l"(r) : "f"(lo), "f"(hi));
    return r;
}
__device__ __forceinline__ u64 dup2(float v) { return pack2(v, v); }

__device__ __forceinline__ void ffma2(u64& acc, u64 a, u64 b) {
    asm("fma.rn.f32x2 %0, %1, %2, %0;" : "+l"(acc) : "l"(a), "l"(b));
}
__device__ __forceinline__ float2 unpack2(u64 v) {
    float2 f;
    asm("mov.b64 {%0, %1}, %2;" : "=f"(f.x), "=f"(f.y) : "l"(v));
    return f;
}

// ---------------------------------------------------------------------------
// Weight transposes (run every call; tiny).
// Conv: wT[((cog*CI + ci)*9 + tap)*16 + o] = w[((cog*16 + o)*CI + ci)*9 + tap]
// ---------------------------------------------------------------------------
template <int CI>
__global__ void transpose_convw_kernel(const float* __restrict__ w, float* __restrict__ wT)
{
    const int i = blockIdx.x * 256 + threadIdx.x;
    if (i < 64 * CI * 9) {
        const int o   = i & 15;
        const int r   = i >> 4;
        const int tap = r % 9;
        const int r2  = r / 9;
        const int ci  = r2 % CI;
        const int cog = r2 / CI;
        wT[i] = w[((size_t)(cog * 16 + o) * CI + ci) * 9 + tap];
    }
}

// DCN: wT[cc*4608 + l*64 + o] = wd[o][cc*8 + l/9][l%9]
__global__ void transpose_wdcn_kernel(const float* __restrict__ wd, float* __restrict__ wT)
{
    const int i = blockIdx.x * 256 + threadIdx.x;
    if (i < NF * NF * 9) {
        const int cc = i / 4608;
        const int r  = i - cc * 4608;
        const int l  = r >> 6;
        const int o  = r & 63;
        wT[i] = wd[(size_t)o * 576 + cc * 72 + l];
    }
}

// ---------------------------------------------------------------------------
// 3x3 conv + leaky ReLU, 16 output channels per block (8 f32x2 pairs),
// 4 px per thread. Block: 128 thr = 32 x-groups x 4 rows. Grid: (32, 4, B).
// Weights pre-transposed [cog][ci][tap][o16]; staged to smem in 32-ci chunks
// (contiguous float4 copy); fetched by warp-uniform LDS.128 (ulonglong2).
// ---------------------------------------------------------------------------
template <int CI, bool CONCAT>
__global__ __launch_bounds__(128, 4)
void conv3x3w_kernel(const float* __restrict__ inA, const float* __restrict__ inB,
                     const float* __restrict__ wT, const float* __restrict__ bias,
                     float* __restrict__ out)
{
    constexpr int CICHUNK = 32;
    __shared__ __align__(16) float sw[CICHUNK * 9 * 16];     // 18 KB
    const int t   = threadIdx.x;
    const int cog = blockIdx.y;
    const int b   = blockIdx.z;

    const int tx = t & 31, ty = t >> 5;
    const int y  = blockIdx.x * 4 + ty;
    const int x0 = tx * 4;

    u64 acc[8][4];                                // [o-pair][px]
#pragma unroll
    for (int pr = 0; pr < 8; pr++)
#pragma unroll
        for (int p = 0; p < 4; p++) acc[pr][p] = 0ULL;

    const bool vt = (y > 0), vb = (y < H - 1), vl = (x0 > 0), vr = (x0 + 4 < W);

    for (int cc0 = 0; cc0 < CI; cc0 += CICHUNK) {
        __syncthreads();
        {   // contiguous staged copy of this ci-chunk's weights
            const float4* src = (const float4*)(wT + ((size_t)cog * CI + cc0) * 144);
            float4* dst = (float4*)sw;
#pragma unroll
            for (int i = t; i < CICHUNK * 36; i += 128) dst[i] = src[i];
        }
        __syncthreads();

        for (int cl = 0; cl < CICHUNK; cl++) {
            const int ci = cc0 + cl;
            const float* p;
            if (CONCAT)
                p = (ci < NF) ? (inA + ((size_t)b * NF + ci) * HW)
                              : (inB + ((size_t)b * NF + (ci - NF)) * HW);
            else
                p = inA + ((size_t)b * CI + ci) * HW;

            float r[3][6];
            {
                const float* rp = p + y * W;
                float4 v = *(const float4*)(rp + x0);
                r[1][1] = v.x; r[1][2] = v.y; r[1][3] = v.z; r[1][4] = v.w;
                r[1][0] = vl ? rp[x0 - 1] : 0.f;
                r[1][5] = vr ? rp[x0 + 4] : 0.f;
            }
            {
                const float* rp = p + (y - 1) * W;
                float4 v = vt ? *(const float4*)(rp + x0) : make_float4(0.f, 0.f, 0.f, 0.f);
                r[0][1] = v.x; r[0][2] = v.y; r[0][3] = v.z; r[0][4] = v.w;
                r[0][0] = (vt && vl) ? rp[x0 - 1] : 0.f;
                r[0][5] = (vt && vr) ? rp[x0 + 4] : 0.f;
            }
            {
                const float* rp = p + (y + 1) * W;
                float4 v = vb ? *(const float4*)(rp + x0) : make_float4(0.f, 0.f, 0.f, 0.f);
                r[2][1] = v.x; r[2][2] = v.y; r[2][3] = v.z; r[2][4] = v.w;
                r[2][0] = (vb && vl) ? rp[x0 - 1] : 0.f;
                r[2][5] = (vb && vr) ? rp[x0 + 4] : 0.f;
            }

            const float* wci = sw + cl * 144;
#pragma unroll
            for (int dy = 0; dy < 3; dy++) {
                u64 xp[6];
#pragma unroll
                for (int j = 0; j < 6; j++) xp[j] = dup2(r[dy][j]);
#pragma unroll
                for (int dx = 0; dx < 3; dx++) {
                    const ulonglong2* wp = (const ulonglong2*)(wci + (dy * 3 + dx) * 16);
#pragma unroll
                    for (int q = 0; q < 4; q++) {
                        const ulonglong2 wq = wp[q];         // uniform LDS.128
#pragma unroll
                        for (int px = 0; px < 4; px++) {
                            ffma2(acc[2 * q][px],     xp[px + dx], wq.x);
                            ffma2(acc[2 * q + 1][px], xp[px + dx], wq.y);
                        }
                    }
                }
            }
        }
    }

#pragma unroll
    for (int pr = 0; pr < 8; pr++) {
        const int co0 = cog * 16 + 2 * pr;
        const float b0 = bias[co0], b1 = bias[co0 + 1];
        float4 v0, v1;
        float2 u;
        u = unpack2(acc[pr][0]); v0.x = lrelu(u.x + b0); v1.x = lrelu(u.y + b1);
        u = unpack2(acc[pr][1]); v0.y = lrelu(u.x + b0); v1.y = lrelu(u.y + b1);
        u = unpack2(acc[pr][2]); v0.z = lrelu(u.x + b0); v1.z = lrelu(u.y + b1);
        u = unpack2(acc[pr][3]); v0.w = lrelu(u.x + b0); v1.w = lrelu(u.y + b1);
        *(float4*)(out + ((size_t)b * 64 + co0)     * HW + y * W + x0) = v0;
        *(float4*)(out + ((size_t)b * 64 + co0 + 1) * HW + y * W + x0) = v1;
    }
}

// ---------------------------------------------------------------------------
// Offset/mask head: 3x3 conv 64 -> 27 (slice of 9 = 4 o-pairs + 1 scalar).
// Block: 128 threads = 64 x-groups (2 px) x 2 rows. Grid: (64, 3, B).
// ---------------------------------------------------------------------------
__global__ __launch_bounds__(128, 8)
void conv_offset_kernel(const float* __restrict__ in, const float* __restrict__ w,
                        const float* __restrict__ bias,
                        float* __restrict__ off_out, float* __restrict__ mask_out)
{
    constexpr int CI = 64;
    __shared__ float sw[CI * 9 * 10];             // [ci][tap][o pad10]
    const int t   = threadIdx.x;
    const int cog = blockIdx.y;
    const int b   = blockIdx.z;

    const float* wsrc = w + (size_t)cog * 9 * CI * 9;
    for (int i = t; i < 9 * CI * 9; i += 128) {
        const int o = i / (CI * 9);
        const int rest = i - o * (CI * 9);
        sw[rest * 10 + o] = wsrc[o * (CI * 9) + rest];
    }
    __syncthreads();

    const int tx = t & 63, ty = t >> 6;
    const int y  = blockIdx.x * 2 + ty;
    const int x0 = tx * 2;

    u64 accp[4][2];
    float accs[2];
#pragma unroll
    for (int pr = 0; pr < 4; pr++) { accp[pr][0] = 0ULL; accp[pr][1] = 0ULL; }
    accs[0] = accs[1] = 0.f;

    const bool vt = (y > 0), vb = (y < H - 1), vl = (x0 > 0), vr = (x0 + 2 < W);

    for (int ci = 0; ci < CI; ci++) {
        const float* p = in + ((size_t)b * CI + ci) * HW;
        float r[3][4];
        {
            const float* rp = p + y * W;
            float2 v = *(const float2*)(rp + x0);
            r[1][1] = v.x; r[1][2] = v.y;
            r[1][0] = vl ? rp[x0 - 1] : 0.f;
            r[1][3] = vr ? rp[x0 + 2] : 0.f;
        }
        {
            const float* rp = p + (y - 1) * W;
            float2 v = vt ? *(const float2*)(rp + x0) : make_float2(0.f, 0.f);
            r[0][1] = v.x; r[0][2] = v.y;
            r[0][0] = (vt && vl) ? rp[x0 - 1] : 0.f;
            r[0][3] = (vt && vr) ? rp[x0 + 2] : 0.f;
        }
        {
            const float* rp = p + (y + 1) * W;
            float2 v = vb ? *(const float2*)(rp + x0) : make_float2(0.f, 0.f);
            r[2][1] = v.x; r[2][2] = v.y;
            r[2][0] = (vb && vl) ? rp[x0 - 1] : 0.f;
            r[2][3] = (vb && vr) ? rp[x0 + 2] : 0.f;
        }

        const float* wci = sw + ci * 90;
#pragma unroll
        for (int dy = 0; dy < 3; dy++) {
            u64 xp[4];
#pragma unroll
            for (int j = 0; j < 4; j++) xp[j] = dup2(r[dy][j]);
#pragma unroll
            for (int dx = 0; dx < 3; dx++) {
                const int tap = dy * 3 + dx;
                const u64* wp = (const u64*)(wci + tap * 10);
                u64 wv[4];
#pragma unroll
                for (int pr = 0; pr < 4; pr++) wv[pr] = wp[pr];
                const float ws = wci[tap * 10 + 8];
#pragma unroll
                for (int px = 0; px < 2; px++) {
#pragma unroll
                    for (int pr = 0; pr < 4; pr++)
                        ffma2(accp[pr][px], xp[px + dx], wv[pr]);
                    accs[px] = fmaf(r[dy][px + dx], ws, accs[px]);
                }
            }
        }
    }

    const bool is_off = (cog < 2);
    float vals[9][2];
#pragma unroll
    for (int pr = 0; pr < 4; pr++) {
        const int co = cog * 9 + 2 * pr;
        const float b0 = bias[co], b1 = bias[co + 1];
#pragma unroll
        for (int px = 0; px < 2; px++) {
            float2 u = unpack2(accp[pr][px]);
            vals[2 * pr][px]     = u.x + b0;
            vals[2 * pr + 1][px] = u.y + b1;
        }
    }
    {
        const float bb = bias[cog * 9 + 8];
        vals[8][0] = accs[0] + bb;
        vals[8][1] = accs[1] + bb;
    }

#pragma unroll
    for (int o = 0; o < 9; o++) {
        const int co = cog * 9 + o;
        float2 v;
        if (is_off) {
            v.x = 15.f * tanhf(vals[o][0]);
            v.y = 15.f * tanhf(vals[o][1]);
            *(float2*)(off_out + ((size_t)b * 18 + co) * HW + y * W + x0) = v;
        } else {
            v.x = 1.f / (1.f + expf(-vals[o][0]));
            v.y = 1.f / (1.f + expf(-vals[o][1]));
            *(float2*)(mask_out + ((size_t)b * 9 + (co - 18)) * HW + y * W + x0) = v;
        }
    }
}

// ---------------------------------------------------------------------------
// Modulated deformable conv (DCNv2) + leaky ReLU.
// Block: 128 threads (4 warps), tile = 64 px of one row, all 64 co.
// GEMM: lane owns px-pair; warp owns 16 oc (8 pairs via 4 uniform LDS.128).
// Grid: (2, 128, 4). Dynamic smem 54 KB -> 4 CTAs/SM.
// ---------------------------------------------------------------------------
__global__ __launch_bounds__(128, 4)
void dcn_kernel(const float* __restrict__ x, const float* __restrict__ offs,
                const float* __restrict__ mask, const float* __restrict__ wT,
                const float* __restrict__ bias, float* __restrict__ out)
{
    extern __shared__ __align__(16) char smem_raw[];
    int*   sIdx = (int*)smem_raw;                    // [4][9][64]   9216 B
    float* sWt  = (float*)(smem_raw + 9216);         // [4][9][64]   9216 B
    float* sS   = (float*)(smem_raw + 18432);        // [72][64]    18432 B
    float* sWd  = (float*)(smem_raw + 36864);        // [72][64]    18432 B

    const int t  = threadIdx.x;
    const int x0 = blockIdx.x * 64;
    const int y  = blockIdx.y;
    const int b  = blockIdx.z;

    // Stage 0: tap descriptors
    for (int i = t; i < 64 * K; i += 128) {
        const int px = i & 63;
        const int k  = i >> 6;
        const int xx = x0 + px;
        const int base = y * W + xx;
        const float oy = offs[((size_t)b * 18 + 2 * k) * HW + base];
        const float ox = offs[((size_t)b * 18 + 2 * k + 1) * HW + base];
        const float m  = mask[((size_t)b * K + k) * HW + base];
        const float py  = (float)(y + k / 3 - 1) + oy;
        const float pxx = (float)(xx + k % 3 - 1) + ox;
        const float fy = floorf(py), fx = floorf(pxx);
        const float wy = py - fy,  wx = pxx - fx;
        const int iy0 = (int)fy, ix0 = (int)fx;
#pragma unroll
        for (int c2 = 0; c2 < 4; c2++) {
            const int yy = iy0 + (c2 >> 1);
            const int xc = ix0 + (c2 & 1);
            const bool v = (yy >= 0) && (yy < H) && (xc >= 0) && (xc < W);
            const float wgt = ((c2 >> 1) ? wy : 1.f - wy) * ((c2 & 1) ? wx : 1.f - wx) * m;
            sIdx[(c2 * K + k) * 64 + px] = v ? (yy * W + xc) : 0;
            sWt [(c2 * K + k) * 64 + px] = v ? wgt : 0.f;
        }
    }
    __syncthreads();

    const int lane = t & 31;
    const int og   = t >> 5;                         // 0..3 -> 16 oc each
    u64 accA[8], accB[8];                            // [o-pair] for px0, px1
#pragma unroll
    for (int pr = 0; pr < 8; pr++) { accA[pr] = 0ULL; accB[pr] = 0ULL; }

    for (int cc = 0; cc < 8; cc++) {
        // stage weight chunk [l][o]: contiguous float4 copy (18 KB)
        {
            const float4* src = (const float4*)(wT + cc * 4608);
            float4* dst = (float4*)sWd;
#pragma unroll
            for (int i = t; i < 1152; i += 128) dst[i] = src[i];
        }
        // compute S chunk (gather + bilinear/mask combine)
        const float* xb = x + ((size_t)b * NF + cc * 8) * HW;
        for (int i = t; i < 72 * 64; i += 128) {
            const int px = i & 63;
            const int l  = i >> 6;           // 0..71 : (c_local, k)
            const int c  = l / 9, k = l - c * 9;
            const float* xp = xb + (size_t)c * HW;
            float s = 0.f;
#pragma unroll
            for (int c2 = 0; c2 < 4; c2++)
                s = fmaf(sWt[(c2 * K + k) * 64 + px],
                         __ldg(xp + sIdx[(c2 * K + k) * 64 + px]), s);
            sS[l * 64 + px] = s;
        }
        __syncthreads();

        const u64* sS64 = (const u64*)sS;
#pragma unroll 4
        for (int l = 0; l < 72; l++) {
            const u64 s = sS64[l * 32 + lane];       // {s_px0, s_px1}
            float2 f = unpack2(s);
            const u64 d0 = dup2(f.x), d1 = dup2(f.y);
            const ulonglong2* wp = (const ulonglong2*)(sWd + l * 64 + og * 16);
#pragma unroll
            for (int q = 0; q < 4; q++) {
                const ulonglong2 wq = wp[q];         // uniform LDS.128
                ffma2(accA[2 * q],     d0, wq.x);
                ffma2(accA[2 * q + 1], d0, wq.y);
                ffma2(accB[2 * q],     d1, wq.x);
                ffma2(accB[2 * q + 1], d1, wq.y);
            }
        }
        __syncthreads();
    }

    const int pxg = x0 + 2 * lane;
#pragma unroll
    for (int pr = 0; pr < 8; pr++) {
        const int co = og * 16 + 2 * pr;
        const float b0 = bias[co], b1 = bias[co + 1];
        float2 a = unpack2(accA[pr]);
        float2 bb = unpack2(accB[pr]);
        float2 v0, v1;
        v0.x = lrelu(a.x + b0);  v0.y = lrelu(bb.x + b0);
        v1.x = lrelu(a.y + b1);  v1.y = lrelu(bb.y + b1);
        *(float2*)(out + ((size_t)b * NF + co)     * HW + y * W + pxg) = v0;
        *(float2*)(out + ((size_t)b * NF + co + 1) * HW + y * W + pxg) = v1;
    }
}

// ---------------------------------------------------------------------------
extern "C" void kernel_launch(void* const* d_in, const int* in_sizes, int n_in,
                              void* d_out, int out_size)
{
    const float* nbr   = (const float*)d_in[0];
    const float* ref   = (const float*)d_in[1];
    const float* w1    = (const float*)d_in[2];
    const float* b1    = (const float*)d_in[3];
    const float* w2    = (const float*)d_in[4];
    const float* b2    = (const float*)d_in[5];
    const float* w3    = (const float*)d_in[6];
    const float* b3    = (const float*)d_in[7];
    const float* w_off = (const float*)d_in[8];
    const float* b_off = (const float*)d_in[9];
    const float* w_dcn = (const float*)d_in[10];
    const float* b_dcn = (const float*)d_in[11];

    float* out  = (float*)d_out;
    float* feat = out;                                   // [B,64,H,W]
    float* offs = out + (size_t)BN * NF * HW;            // [B,18,H,W]
    float* msk  = offs + (size_t)BN * 18 * HW;           // [B, 9,H,W]

    float *bufA, *bufB, *w1T, *w2T, *w3T, *wdT;
    cudaGetSymbolAddress((void**)&bufA, g_bufA);
    cudaGetSymbolAddress((void**)&bufB, g_bufB);
    cudaGetSymbolAddress((void**)&w1T,  g_w1T);
    cudaGetSymbolAddress((void**)&w2T,  g_w2T);
    cudaGetSymbolAddress((void**)&w3T,  g_w3T);
    cudaGetSymbolAddress((void**)&wdT,  g_wdT);

    transpose_convw_kernel<128><<<(64 * 128 * 9 + 255) / 256, 256>>>(w1, w1T);
    transpose_convw_kernel< 64><<<(64 *  64 * 9 + 255) / 256, 256>>>(w2, w2T);
    transpose_convw_kernel< 64><<<(64 *  64 * 9 + 255) / 256, 256>>>(w3, w3T);
    transpose_wdcn_kernel<<<(NF * NF * 9 + 255) / 256, 256>>>(w_dcn, wdT);

    conv3x3w_kernel<128, true ><<<dim3(32, 4, 4), 128>>>(nbr, ref, w1T, b1, bufA);
    conv3x3w_kernel< 64, false><<<dim3(32, 4, 4), 128>>>(bufA, bufA, w2T, b2, bufB);
    conv3x3w_kernel< 64, false><<<dim3(32, 4, 4), 128>>>(bufB, bufB, w3T, b3, bufA);
    conv_offset_kernel<<<dim3(64, 3, 4), 128>>>(bufA, w_off, b_off, offs, msk);

    const int dcn_smem = 9216 + 9216 + 18432 + 18432;    // 55296 B
    cudaFuncSetAttribute(dcn_kernel, cudaFuncAttributeMaxDynamicSharedMemorySize, dcn_smem);
    dcn_kernel<<<dim3(2, 128, 4), 128, dcn_smem>>>(nbr, offs, msk, wdT, b_dcn, feat);
}

// round 6
// speedup vs baseline: 1.3414x; 1.3414x over previous
#include <cuda_runtime.h>
#include <cuda_bf16.h>
#include <math.h>

// Problem constants
constexpr int BN = 4;
constexpr int NF = 64;
constexpr int H  = 128;
constexpr int W  = 128;
constexpr int HW = H * W;
constexpr int K  = 9;

// Scratch (device globals: no runtime allocation allowed)
__device__ float g_bufA[BN * NF * HW];
__device__ float g_bufB[BN * NF * HW];
__device__ float g_wdT[NF * NF * 9];                 // DCN weights [cc][l][o]
__device__ __nv_bfloat16 g_A1[2 * 9 * 2 * 64 * 72]; // conv1 mma weights (hi/lo, pad72)
__device__ __nv_bfloat16 g_A2[1 * 9 * 2 * 64 * 72];
__device__ __nv_bfloat16 g_A3[1 * 9 * 2 * 64 * 72];

__device__ __forceinline__ float lrelu(float v) { return v >= 0.f ? v : 0.1f * v; }

// ---- packed f32x2 helpers (fp32 kernels) -----------------------------------
using u64 = unsigned long long;
__device__ __forceinline__ u64 pack2(float lo, float hi) {
    u64 r; asm("mov.b64 %0, {%1, %2};" : "=l"(r) : "f"(lo), "f"(hi)); return r;
}
__device__ __forceinline__ u64 dup2(float v) { return pack2(v, v); }
__device__ __forceinline__ void ffma2(u64& acc, u64 a, u64 b) {
    asm("fma.rn.f32x2 %0, %1, %2, %0;" : "+l"(acc) : "l"(a), "l"(b));
}
__device__ __forceinline__ float2 unpack2(u64 v) {
    float2 f; asm("mov.b64 {%0, %1}, %2;" : "=f"(f.x), "=f"(f.y) : "l"(v)); return f;
}

// ---- mma.sync helpers ------------------------------------------------------
__device__ __forceinline__ unsigned smem_u32(const void* p) {
    unsigned a;
    asm("{ .reg .u64 t; cvta.to.shared.u64 t, %1; cvt.u32.u64 %0, t; }" : "=r"(a) : "l"(p));
    return a;
}
__device__ __forceinline__ void ldsm4(unsigned* a, unsigned saddr) {
    asm volatile("ldmatrix.sync.aligned.m8n8.x4.shared.b16 {%0,%1,%2,%3}, [%4];"
                 : "=r"(a[0]), "=r"(a[1]), "=r"(a[2]), "=r"(a[3]) : "r"(saddr));
}
__device__ __forceinline__ void mma16816(float* c, const unsigned* a, unsigned b0, unsigned b1) {
    asm volatile(
        "mma.sync.aligned.m16n8k16.row.col.f32.bf16.bf16.f32 "
        "{%0,%1,%2,%3}, {%4,%5,%6,%7}, {%8,%9}, {%0,%1,%2,%3};"
        : "+f"(c[0]), "+f"(c[1]), "+f"(c[2]), "+f"(c[3])
        : "r"(a[0]), "r"(a[1]), "r"(a[2]), "r"(a[3]), "r"(b0), "r"(b1));
}

// ---------------------------------------------------------------------------
// Prep: conv weights -> per-(cc,tap) A blocks [hi:64x72][lo:64x72] bf16.
//   A[m=oc][k=ci_local], row stride 72 (bank-conflict-free ldmatrix).
// ---------------------------------------------------------------------------
template <int CC>
__global__ void prep_mma_w(const float* __restrict__ w, __nv_bfloat16* __restrict__ A)
{
    constexpr int CI = CC * 64;
    const int i = blockIdx.x * 256 + threadIdx.x;
    if (i >= CC * 9 * 2 * 4096) return;
    const int k   = i & 63;
    const int m   = (i >> 6) & 63;
    const int bt  = i >> 12;
    const int var = bt & 1;
    const int ct  = bt >> 1;            // cc*9 + tap
    const int tap = ct % 9;
    const int cc  = ct / 9;
    const float wv = w[((size_t)m * CI + cc * 64 + k) * 9 + tap];
    const __nv_bfloat16 h = __float2bfloat16(wv);
    const __nv_bfloat16 val = var ? __float2bfloat16(wv - __bfloat162float(h)) : h;
    A[(size_t)ct * 9216 + var * 4608 + m * 72 + k] = val;
}

// DCN: wT[cc*4608 + l*64 + o] = wd[o][cc*8 + l/9][l%9]
__global__ void transpose_wdcn_kernel(const float* __restrict__ wd, float* __restrict__ wT)
{
    const int i = blockIdx.x * 256 + threadIdx.x;
    if (i < NF * NF * 9) {
        const int cc = i / 4608;
        const int r  = i - cc * 4608;
        const int l  = r >> 6;
        const int o  = r & 63;
        wT[i] = wd[(size_t)o * 576 + cc * 72 + l];
    }
}

// ---------------------------------------------------------------------------
// HMMA conv3x3 + bias + leaky ReLU (bf16 3-term split: hh + h*lo + lo*h).
// Block: 256 thr, tile = 2 rows x 64 px x 64 oc. Grid: (2, H/2, B).
// smem: B = 4 input rows (y0-1..y0+2) x {hi,lo} x [66 px][ci pad68] bf16;
//       A staged per tap: [hi 64x72][lo 64x72].
// dx shift handled in the B fragment smem address (halo px index + dx).
// Warp: 32 oc (2 m-tiles) x 16 px (2 n-tiles) x 2 rows; 8 warps = 2 ocg x 4 pxg.
// ---------------------------------------------------------------------------
constexpr int BT_BYTES = 66 * 68 * 2;          // 8976 per tile
constexpr int A_OFF    = 8 * BT_BYTES;         // 71808
constexpr int CSM_SIZE = A_OFF + 2 * 64 * 72 * 2;  // 90240

template <int CC, bool CONCAT>
__global__ __launch_bounds__(256, 2)
void conv_mma_kernel(const float* __restrict__ inA, const float* __restrict__ inB,
                     const __nv_bfloat16* __restrict__ Aw, const float* __restrict__ bias,
                     float* __restrict__ out)
{
    extern __shared__ __align__(16) char smem[];
    const unsigned sbase = smem_u32(smem);
    const int t    = threadIdx.x;
    const int wid  = t >> 5;
    const int lane = t & 31;
    const int x0   = blockIdx.x * 64;
    const int y0   = blockIdx.y * 2;
    const int b    = blockIdx.z;

    const int ocg = wid & 1;                    // 0/1 -> oc base 32*ocg
    const int pxg = wid >> 1;                   // 0..3 -> px base 16*pxg

    float acc[2][2][2][4];                      // [r][mt][nt][4]
#pragma unroll
    for (int r = 0; r < 2; r++)
#pragma unroll
        for (int mt = 0; mt < 2; mt++)
#pragma unroll
            for (int nt = 0; nt < 2; nt++)
#pragma unroll
                for (int c = 0; c < 4; c++) acc[r][mt][nt][c] = 0.f;

    for (int cc = 0; cc < CC; cc++) {
        if (cc) __syncthreads();
        // ---- stage B: 4 rows x 64 ci x 66 px (halo), hi/lo bf16
        const float* src = CONCAT ? (cc ? inB : inA) : inA;
        for (int i = t; i < 4 * 64 * 66; i += 256) {
            const int pxi = i % 66;
            const int rci = i / 66;
            const int ci  = rci & 63;
            const int d   = rci >> 6;           // 0..3 -> row y0+d-1
            const int row = y0 + d - 1;
            const int xg  = x0 + pxi - 1;
            float v = 0.f;
            if (row >= 0 && row < H && xg >= 0 && xg < W)
                v = src[((size_t)b * 64 + ci) * HW + row * W + xg];
            const __nv_bfloat16 h = __float2bfloat16(v);
            const __nv_bfloat16 l = __float2bfloat16(v - __bfloat162float(h));
            const int eo = (pxi * 68 + ci) * 2;
            *(__nv_bfloat16*)(smem + (d * 2)     * BT_BYTES + eo) = h;
            *(__nv_bfloat16*)(smem + (d * 2 + 1) * BT_BYTES + eo) = l;
        }
        __syncthreads();

        for (int tap = 0; tap < 9; tap++) {
            if (tap) __syncthreads();
            // ---- stage A (hi+lo, 18432 B contiguous)
            {
                const uint4* srcw = (const uint4*)((const char*)Aw + (size_t)(cc * 9 + tap) * 18432);
                uint4* dst = (uint4*)(smem + A_OFF);
                for (int i = t; i < 1152; i += 256) dst[i] = srcw[i];
            }
            __syncthreads();

            const int dy = tap / 3, dx = tap - dy * 3;
#pragma unroll 1
            for (int ks = 0; ks < 4; ks++) {
                unsigned Ah[2][4], Al[2][4];
#pragma unroll
                for (int mt = 0; mt < 2; mt++) {
                    const unsigned ao = A_OFF +
                        ((ocg * 32 + mt * 16 + (lane & 15)) * 72 + ks * 16 + (lane >> 4) * 8) * 2;
                    ldsm4(Ah[mt], sbase + ao);
                    ldsm4(Al[mt], sbase + ao + 9216);
                }
#pragma unroll
                for (int r = 0; r < 2; r++) {
                    const char* Bh = smem + ((r + dy) * 2)     * BT_BYTES;
                    const char* Bl = smem + ((r + dy) * 2 + 1) * BT_BYTES;
#pragma unroll
                    for (int nt = 0; nt < 2; nt++) {
                        const int pxi  = pxg * 16 + nt * 8 + (lane >> 2) + dx;
                        const int koff = ks * 16 + 2 * (lane & 3);
                        const int eo   = (pxi * 68 + koff) * 2;
                        const unsigned bh0 = *(const unsigned*)(Bh + eo);
                        const unsigned bh1 = *(const unsigned*)(Bh + eo + 16);
                        const unsigned bl0 = *(const unsigned*)(Bl + eo);
                        const unsigned bl1 = *(const unsigned*)(Bl + eo + 16);
#pragma unroll
                        for (int mt = 0; mt < 2; mt++) {
                            mma16816(acc[r][mt][nt], Ah[mt], bh0, bh1);
                            mma16816(acc[r][mt][nt], Ah[mt], bl0, bl1);
                            mma16816(acc[r][mt][nt], Al[mt], bh0, bh1);
                        }
                    }
                }
            }
        }
    }

    // ---- epilogue: c-frag (m=lane>>2 (+8), n=2*(lane&3)+{0,1})
#pragma unroll
    for (int mt = 0; mt < 2; mt++) {
        const int ocA = ocg * 32 + mt * 16 + (lane >> 2);
        const int ocB = ocA + 8;
        const float bA = __ldg(bias + ocA);
        const float bB = __ldg(bias + ocB);
#pragma unroll
        for (int r = 0; r < 2; r++) {
            const int row = y0 + r;
#pragma unroll
            for (int nt = 0; nt < 2; nt++) {
                const int px = x0 + pxg * 16 + nt * 8 + 2 * (lane & 3);
                const float* c = acc[r][mt][nt];
                float2 vA, vB;
                vA.x = lrelu(c[0] + bA); vA.y = lrelu(c[1] + bA);
                vB.x = lrelu(c[2] + bB); vB.y = lrelu(c[3] + bB);
                *(float2*)(out + ((size_t)b * 64 + ocA) * HW + row * W + px) = vA;
                *(float2*)(out + ((size_t)b * 64 + ocB) * HW + row * W + px) = vB;
            }
        }
    }
}

// ---------------------------------------------------------------------------
// Offset/mask head (fp32 FFMA2, known good).
// ---------------------------------------------------------------------------
__global__ __launch_bounds__(128, 8)
void conv_offset_kernel(const float* __restrict__ in, const float* __restrict__ w,
                        const float* __restrict__ bias,
                        float* __restrict__ off_out, float* __restrict__ mask_out)
{
    constexpr int CI = 64;
    __shared__ float sw[CI * 9 * 10];
    const int t   = threadIdx.x;
    const int cog = blockIdx.y;
    const int b   = blockIdx.z;

    const float* wsrc = w + (size_t)cog * 9 * CI * 9;
    for (int i = t; i < 9 * CI * 9; i += 128) {
        const int o = i / (CI * 9);
        const int rest = i - o * (CI * 9);
        sw[rest * 10 + o] = wsrc[o * (CI * 9) + rest];
    }
    __syncthreads();

    const int tx = t & 63, ty = t >> 6;
    const int y  = blockIdx.x * 2 + ty;
    const int x0 = tx * 2;

    u64 accp[4][2];
    float accs[2];
#pragma unroll
    for (int pr = 0; pr < 4; pr++) { accp[pr][0] = 0ULL; accp[pr][1] = 0ULL; }
    accs[0] = accs[1] = 0.f;

    const bool vt = (y > 0), vb = (y < H - 1), vl = (x0 > 0), vr = (x0 + 2 < W);

    for (int ci = 0; ci < CI; ci++) {
        const float* p = in + ((size_t)b * CI + ci) * HW;
        float r[3][4];
        {
            const float* rp = p + y * W;
            float2 v = *(const float2*)(rp + x0);
            r[1][1] = v.x; r[1][2] = v.y;
            r[1][0] = vl ? rp[x0 - 1] : 0.f;
            r[1][3] = vr ? rp[x0 + 2] : 0.f;
        }
        {
            const float* rp = p + (y - 1) * W;
            float2 v = vt ? *(const float2*)(rp + x0) : make_float2(0.f, 0.f);
            r[0][1] = v.x; r[0][2] = v.y;
            r[0][0] = (vt && vl) ? rp[x0 - 1] : 0.f;
            r[0][3] = (vt && vr) ? rp[x0 + 2] : 0.f;
        }
        {
            const float* rp = p + (y + 1) * W;
            float2 v = vb ? *(const float2*)(rp + x0) : make_float2(0.f, 0.f);
            r[2][1] = v.x; r[2][2] = v.y;
            r[2][0] = (vb && vl) ? rp[x0 - 1] : 0.f;
            r[2][3] = (vb && vr) ? rp[x0 + 2] : 0.f;
        }

        const float* wci = sw + ci * 90;
#pragma unroll
        for (int dy = 0; dy < 3; dy++) {
            u64 xp[4];
#pragma unroll
            for (int j = 0; j < 4; j++) xp[j] = dup2(r[dy][j]);
#pragma unroll
            for (int dx = 0; dx < 3; dx++) {
                const int tap = dy * 3 + dx;
                const u64* wp = (const u64*)(wci + tap * 10);
                u64 wv[4];
#pragma unroll
                for (int pr = 0; pr < 4; pr++) wv[pr] = wp[pr];
                const float ws = wci[tap * 10 + 8];
#pragma unroll
                for (int px = 0; px < 2; px++) {
#pragma unroll
                    for (int pr = 0; pr < 4; pr++)
                        ffma2(accp[pr][px], xp[px + dx], wv[pr]);
                    accs[px] = fmaf(r[dy][px + dx], ws, accs[px]);
                }
            }
        }
    }

    const bool is_off = (cog < 2);
    float vals[9][2];
#pragma unroll
    for (int pr = 0; pr < 4; pr++) {
        const int co = cog * 9 + 2 * pr;
        const float b0 = bias[co], b1 = bias[co + 1];
#pragma unroll
        for (int px = 0; px < 2; px++) {
            float2 u = unpack2(accp[pr][px]);
            vals[2 * pr][px]     = u.x + b0;
            vals[2 * pr + 1][px] = u.y + b1;
        }
    }
    {
        const float bb = bias[cog * 9 + 8];
        vals[8][0] = accs[0] + bb;
        vals[8][1] = accs[1] + bb;
    }

#pragma unroll
    for (int o = 0; o < 9; o++) {
        const int co = cog * 9 + o;
        float2 v;
        if (is_off) {
            v.x = 15.f * tanhf(vals[o][0]);
            v.y = 15.f * tanhf(vals[o][1]);
            *(float2*)(off_out + ((size_t)b * 18 + co) * HW + y * W + x0) = v;
        } else {
            v.x = 1.f / (1.f + expf(-vals[o][0]));
            v.y = 1.f / (1.f + expf(-vals[o][1]));
            *(float2*)(mask_out + ((size_t)b * 9 + (co - 18)) * HW + y * W + x0) = v;
        }
    }
}

// ---------------------------------------------------------------------------
// Modulated deformable conv (DCNv2) + leaky ReLU (fp32 FFMA2, known good).
// ---------------------------------------------------------------------------
__global__ __launch_bounds__(256, 4)
void dcn_kernel(const float* __restrict__ x, const float* __restrict__ offs,
                const float* __restrict__ mask, const float* __restrict__ wT,
                const float* __restrict__ bias, float* __restrict__ out)
{
    extern __shared__ char smem_raw[];
    int*   sIdx = (int*)smem_raw;                    // [4][9][64]   9216 B
    float* sWt  = (float*)(smem_raw + 9216);         // [4][9][64]   9216 B
    float* sS   = (float*)(smem_raw + 18432);        // [72][64]    18432 B
    float* sWd  = (float*)(smem_raw + 36864);        // [72][64]    18432 B

    const int t  = threadIdx.x;
    const int x0 = blockIdx.x * 64;
    const int y  = blockIdx.y;
    const int b  = blockIdx.z;

    for (int i = t; i < 64 * K; i += 256) {
        const int px = i & 63;
        const int k  = i >> 6;
        const int xx = x0 + px;
        const int base = y * W + xx;
        const float oy = offs[((size_t)b * 18 + 2 * k) * HW + base];
        const float ox = offs[((size_t)b * 18 + 2 * k + 1) * HW + base];
        const float m  = mask[((size_t)b * K + k) * HW + base];
        const float py  = (float)(y + k / 3 - 1) + oy;
        const float pxx = (float)(xx + k % 3 - 1) + ox;
        const float fy = floorf(py), fx = floorf(pxx);
        const float wy = py - fy,  wx = pxx - fx;
        const int iy0 = (int)fy, ix0 = (int)fx;
#pragma unroll
        for (int c2 = 0; c2 < 4; c2++) {
            const int yy = iy0 + (c2 >> 1);
            const int xc = ix0 + (c2 & 1);
            const bool v = (yy >= 0) && (yy < H) && (xc >= 0) && (xc < W);
            const float wgt = ((c2 >> 1) ? wy : 1.f - wy) * ((c2 & 1) ? wx : 1.f - wx) * m;
            sIdx[(c2 * K + k) * 64 + px] = v ? (yy * W + xc) : 0;
            sWt [(c2 * K + k) * 64 + px] = v ? wgt : 0.f;
        }
    }
    __syncthreads();

    const int lane = t & 31;
    const int og   = t >> 5;
    u64 accA[4], accB[4];
#pragma unroll
    for (int pr = 0; pr < 4; pr++) { accA[pr] = 0ULL; accB[pr] = 0ULL; }

    for (int cc = 0; cc < 8; cc++) {
        const float* wsrc = wT + cc * 4608;
        for (int i = t; i < 4608; i += 256) sWd[i] = wsrc[i];

        const float* xb = x + ((size_t)b * NF + cc * 8) * HW;
        for (int i = t; i < 72 * 64; i += 256) {
            const int px = i & 63;
            const int l  = i >> 6;
            const int c  = l / 9, k = l - c * 9;
            const float* xp = xb + (size_t)c * HW;
            float s = 0.f;
#pragma unroll
            for (int c2 = 0; c2 < 4; c2++)
                s = fmaf(sWt[(c2 * K + k) * 64 + px],
                         __ldg(xp + sIdx[(c2 * K + k) * 64 + px]), s);
            sS[l * 64 + px] = s;
        }
        __syncthreads();

        const u64* sS64 = (const u64*)sS;
#pragma unroll 4
        for (int l = 0; l < 72; l++) {
            const u64 s = sS64[l * 32 + lane];
            float2 f = unpack2(s);
            const u64 d0 = dup2(f.x), d1 = dup2(f.y);
            const u64* wp = (const u64*)(sWd + l * 64 + og * 8);
#pragma unroll
            for (int pr = 0; pr < 4; pr++) {
                const u64 wv = wp[pr];
                ffma2(accA[pr], d0, wv);
                ffma2(accB[pr], d1, wv);
            }
        }
        __syncthreads();
    }

    const int pxg = x0 + 2 * lane;
#pragma unroll
    for (int pr = 0; pr < 4; pr++) {
        const int co = og * 8 + 2 * pr;
        const float b0 = bias[co], b1 = bias[co + 1];
        float2 a = unpack2(accA[pr]);
        float2 bb = unpack2(accB[pr]);
        float2 v0, v1;
        v0.x = lrelu(a.x + b0);  v0.y = lrelu(bb.x + b0);
        v1.x = lrelu(a.y + b1);  v1.y = lrelu(bb.y + b1);
        *(float2*)(out + ((size_t)b * NF + co)     * HW + y * W + pxg) = v0;
        *(float2*)(out + ((size_t)b * NF + co + 1) * HW + y * W + pxg) = v1;
    }
}

// ---------------------------------------------------------------------------
extern "C" void kernel_launch(void* const* d_in, const int* in_sizes, int n_in,
                              void* d_out, int out_size)
{
    const float* nbr   = (const float*)d_in[0];
    const float* ref   = (const float*)d_in[1];
    const float* w1    = (const float*)d_in[2];
    const float* b1    = (const float*)d_in[3];
    const float* w2    = (const float*)d_in[4];
    const float* b2    = (const float*)d_in[5];
    const float* w3    = (const float*)d_in[6];
    const float* b3    = (const float*)d_in[7];
    const float* w_off = (const float*)d_in[8];
    const float* b_off = (const float*)d_in[9];
    const float* w_dcn = (const float*)d_in[10];
    const float* b_dcn = (const float*)d_in[11];

    float* out  = (float*)d_out;
    float* feat = out;                                   // [B,64,H,W]
    float* offs = out + (size_t)BN * NF * HW;            // [B,18,H,W]
    float* msk  = offs + (size_t)BN * 18 * HW;           // [B, 9,H,W]

    float *bufA, *bufB, *wdT;
    __nv_bfloat16 *A1, *A2, *A3;
    cudaGetSymbolAddress((void**)&bufA, g_bufA);
    cudaGetSymbolAddress((void**)&bufB, g_bufB);
    cudaGetSymbolAddress((void**)&wdT,  g_wdT);
    cudaGetSymbolAddress((void**)&A1,   g_A1);
    cudaGetSymbolAddress((void**)&A2,   g_A2);
    cudaGetSymbolAddress((void**)&A3,   g_A3);

    prep_mma_w<2><<<576, 256>>>(w1, A1);
    prep_mma_w<1><<<288, 256>>>(w2, A2);
    prep_mma_w<1><<<288, 256>>>(w3, A3);
    transpose_wdcn_kernel<<<(NF * NF * 9 + 255) / 256, 256>>>(w_dcn, wdT);

    cudaFuncSetAttribute(conv_mma_kernel<2, true>,
                         cudaFuncAttributeMaxDynamicSharedMemorySize, CSM_SIZE);
    cudaFuncSetAttribute(conv_mma_kernel<1, false>,
                         cudaFuncAttributeMaxDynamicSharedMemorySize, CSM_SIZE);

    conv_mma_kernel<2, true ><<<dim3(2, 64, 4), 256, CSM_SIZE>>>(nbr, ref, A1, b1, bufA);
    conv_mma_kernel<1, false><<<dim3(2, 64, 4), 256, CSM_SIZE>>>(bufA, bufA, A2, b2, bufB);
    conv_mma_kernel<1, false><<<dim3(2, 64, 4), 256, CSM_SIZE>>>(bufB, bufB, A3, b3, bufA);
    conv_offset_kernel<<<dim3(64, 3, 4), 128>>>(bufA, w_off, b_off, offs, msk);

    const int dcn_smem = 9216 + 9216 + 18432 + 18432;    // 55296 B
    cudaFuncSetAttribute(dcn_kernel, cudaFuncAttributeMaxDynamicSharedMemorySize, dcn_smem);
    dcn_kernel<<<dim3(2, 128, 4), 256, dcn_smem>>>(nbr, offs, msk, wdT, b_dcn, feat);
}

// round 7
// speedup vs baseline: 1.3936x; 1.0389x over previous
#include <cuda_runtime.h>
#include <cuda_bf16.h>
#include <math.h>

// Problem constants
constexpr int BN = 4;
constexpr int NF = 64;
constexpr int H  = 128;
constexpr int W  = 128;
constexpr int HW = H * W;
constexpr int K  = 9;

// Scratch (device globals: no runtime allocation allowed)
__device__ float g_bufA[BN * NF * HW];
__device__ float g_bufB[BN * NF * HW];
__device__ __nv_bfloat16 g_A1[2 * 9 * 2 * 64 * 72]; // conv1 mma weights (hi/lo, pad72)
__device__ __nv_bfloat16 g_A2[1 * 9 * 2 * 64 * 72];
__device__ __nv_bfloat16 g_A3[1 * 9 * 2 * 64 * 72];
__device__ __nv_bfloat16 g_Ad[9 * 2 * 64 * 72];     // DCN mma weights [ch][var][oc][72]

__device__ __forceinline__ float lrelu(float v) { return v >= 0.f ? v : 0.1f * v; }

// ---- packed f32x2 helpers (fp32 kernels) -----------------------------------
using u64 = unsigned long long;
__device__ __forceinline__ u64 pack2(float lo, float hi) {
    u64 r; asm("mov.b64 %0, {%1, %2};" : "=l"(r) : "f"(lo), "f"(hi)); return r;
}
__device__ __forceinline__ u64 dup2(float v) { return pack2(v, v); }
__device__ __forceinline__ void ffma2(u64& acc, u64 a, u64 b) {
    asm("fma.rn.f32x2 %0, %1, %2, %0;" : "+l"(acc) : "l"(a), "l"(b));
}
__device__ __forceinline__ float2 unpack2(u64 v) {
    float2 f; asm("mov.b64 {%0, %1}, %2;" : "=f"(f.x), "=f"(f.y) : "l"(v)); return f;
}

// ---- mma.sync helpers ------------------------------------------------------
__device__ __forceinline__ unsigned smem_u32(const void* p) {
    unsigned a;
    asm("{ .reg .u64 t; cvta.to.shared.u64 t, %1; cvt.u32.u64 %0, t; }" : "=r"(a) : "l"(p));
    return a;
}
__device__ __forceinline__ void ldsm4(unsigned* a, unsigned saddr) {
    asm volatile("ldmatrix.sync.aligned.m8n8.x4.shared.b16 {%0,%1,%2,%3}, [%4];"
                 : "=r"(a[0]), "=r"(a[1]), "=r"(a[2]), "=r"(a[3]) : "r"(saddr));
}
__device__ __forceinline__ void mma16816(float* c, const unsigned* a, unsigned b0, unsigned b1) {
    asm volatile(
        "mma.sync.aligned.m16n8k16.row.col.f32.bf16.bf16.f32 "
        "{%0,%1,%2,%3}, {%4,%5,%6,%7}, {%8,%9}, {%0,%1,%2,%3};"
        : "+f"(c[0]), "+f"(c[1]), "+f"(c[2]), "+f"(c[3])
        : "r"(a[0]), "r"(a[1]), "r"(a[2]), "r"(a[3]), "r"(b0), "r"(b1));
}

// ---------------------------------------------------------------------------
// Prep: conv weights -> per-(cc,tap) A blocks [hi:64x72][lo:64x72] bf16.
// ---------------------------------------------------------------------------
template <int CC>
__global__ void prep_mma_w(const float* __restrict__ w, __nv_bfloat16* __restrict__ A)
{
    constexpr int CI = CC * 64;
    const int i = blockIdx.x * 256 + threadIdx.x;
    if (i >= CC * 9 * 2 * 4096) return;
    const int k   = i & 63;
    const int m   = (i >> 6) & 63;
    const int bt  = i >> 12;
    const int var = bt & 1;
    const int ct  = bt >> 1;            // cc*9 + tap
    const int tap = ct % 9;
    const int cc  = ct / 9;
    const float wv = w[((size_t)m * CI + cc * 64 + k) * 9 + tap];
    const __nv_bfloat16 h = __float2bfloat16(wv);
    const __nv_bfloat16 val = var ? __float2bfloat16(wv - __bfloat162float(h)) : h;
    A[(size_t)ct * 9216 + var * 4608 + m * 72 + k] = val;
}

// DCN weights -> A blocks: A[ch][var][oc][72pad], k = flattened (ci*9+tap) chunked by 64.
__global__ void prep_dcn_w(const float* __restrict__ wd, __nv_bfloat16* __restrict__ A)
{
    const int i = blockIdx.x * 256 + threadIdx.x;
    if (i >= 9 * 2 * 64 * 64) return;
    const int ll  = i & 63;
    const int oc  = (i >> 6) & 63;
    const int var = (i >> 12) & 1;
    const int ch  = i >> 13;
    const float wv = wd[(size_t)oc * 576 + ch * 64 + ll];
    const __nv_bfloat16 h = __float2bfloat16(wv);
    const __nv_bfloat16 val = var ? __float2bfloat16(wv - __bfloat162float(h)) : h;
    A[(size_t)ch * 9216 + var * 4608 + oc * 72 + ll] = val;
}

// ---------------------------------------------------------------------------
// HMMA conv3x3 + bias + leaky ReLU (bf16 3-term split) — unchanged from R6.
// ---------------------------------------------------------------------------
constexpr int BT_BYTES = 66 * 68 * 2;          // 8976 per tile
constexpr int A_OFF    = 8 * BT_BYTES;         // 71808
constexpr int CSM_SIZE = A_OFF + 2 * 64 * 72 * 2;  // 90240

template <int CC, bool CONCAT>
__global__ __launch_bounds__(256, 2)
void conv_mma_kernel(const float* __restrict__ inA, const float* __restrict__ inB,
                     const __nv_bfloat16* __restrict__ Aw, const float* __restrict__ bias,
                     float* __restrict__ out)
{
    extern __shared__ __align__(16) char smem[];
    const unsigned sbase = smem_u32(smem);
    const int t    = threadIdx.x;
    const int wid  = t >> 5;
    const int lane = t & 31;
    const int x0   = blockIdx.x * 64;
    const int y0   = blockIdx.y * 2;
    const int b    = blockIdx.z;

    const int ocg = wid & 1;
    const int pxg = wid >> 1;

    float acc[2][2][2][4];
#pragma unroll
    for (int r = 0; r < 2; r++)
#pragma unroll
        for (int mt = 0; mt < 2; mt++)
#pragma unroll
            for (int nt = 0; nt < 2; nt++)
#pragma unroll
                for (int c = 0; c < 4; c++) acc[r][mt][nt][c] = 0.f;

    for (int cc = 0; cc < CC; cc++) {
        if (cc) __syncthreads();
        const float* src = CONCAT ? (cc ? inB : inA) : inA;
        for (int i = t; i < 4 * 64 * 66; i += 256) {
            const int pxi = i % 66;
            const int rci = i / 66;
            const int ci  = rci & 63;
            const int d   = rci >> 6;
            const int row = y0 + d - 1;
            const int xg  = x0 + pxi - 1;
            float v = 0.f;
            if (row >= 0 && row < H && xg >= 0 && xg < W)
                v = src[((size_t)b * 64 + ci) * HW + row * W + xg];
            const __nv_bfloat16 h = __float2bfloat16(v);
            const __nv_bfloat16 l = __float2bfloat16(v - __bfloat162float(h));
            const int eo = (pxi * 68 + ci) * 2;
            *(__nv_bfloat16*)(smem + (d * 2)     * BT_BYTES + eo) = h;
            *(__nv_bfloat16*)(smem + (d * 2 + 1) * BT_BYTES + eo) = l;
        }
        __syncthreads();

        for (int tap = 0; tap < 9; tap++) {
            if (tap) __syncthreads();
            {
                const uint4* srcw = (const uint4*)((const char*)Aw + (size_t)(cc * 9 + tap) * 18432);
                uint4* dst = (uint4*)(smem + A_OFF);
                for (int i = t; i < 1152; i += 256) dst[i] = srcw[i];
            }
            __syncthreads();

            const int dy = tap / 3, dx = tap - dy * 3;
#pragma unroll 1
            for (int ks = 0; ks < 4; ks++) {
                unsigned Ah[2][4], Al[2][4];
#pragma unroll
                for (int mt = 0; mt < 2; mt++) {
                    const unsigned ao = A_OFF +
                        ((ocg * 32 + mt * 16 + (lane & 15)) * 72 + ks * 16 + (lane >> 4) * 8) * 2;
                    ldsm4(Ah[mt], sbase + ao);
                    ldsm4(Al[mt], sbase + ao + 9216);
                }
#pragma unroll
                for (int r = 0; r < 2; r++) {
                    const char* Bh = smem + ((r + dy) * 2)     * BT_BYTES;
                    const char* Bl = smem + ((r + dy) * 2 + 1) * BT_BYTES;
#pragma unroll
                    for (int nt = 0; nt < 2; nt++) {
                        const int pxi  = pxg * 16 + nt * 8 + (lane >> 2) + dx;
                        const int koff = ks * 16 + 2 * (lane & 3);
                        const int eo   = (pxi * 68 + koff) * 2;
                        const unsigned bh0 = *(const unsigned*)(Bh + eo);
                        const unsigned bh1 = *(const unsigned*)(Bh + eo + 16);
                        const unsigned bl0 = *(const unsigned*)(Bl + eo);
                        const unsigned bl1 = *(const unsigned*)(Bl + eo + 16);
#pragma unroll
                        for (int mt = 0; mt < 2; mt++) {
                            mma16816(acc[r][mt][nt], Ah[mt], bh0, bh1);
                            mma16816(acc[r][mt][nt], Ah[mt], bl0, bl1);
                            mma16816(acc[r][mt][nt], Al[mt], bh0, bh1);
                        }
                    }
                }
            }
        }
    }

#pragma unroll
    for (int mt = 0; mt < 2; mt++) {
        const int ocA = ocg * 32 + mt * 16 + (lane >> 2);
        const int ocB = ocA + 8;
        const float bA = __ldg(bias + ocA);
        const float bB = __ldg(bias + ocB);
#pragma unroll
        for (int r = 0; r < 2; r++) {
            const int row = y0 + r;
#pragma unroll
            for (int nt = 0; nt < 2; nt++) {
                const int px = x0 + pxg * 16 + nt * 8 + 2 * (lane & 3);
                const float* c = acc[r][mt][nt];
                float2 vA, vB;
                vA.x = lrelu(c[0] + bA); vA.y = lrelu(c[1] + bA);
                vB.x = lrelu(c[2] + bB); vB.y = lrelu(c[3] + bB);
                *(float2*)(out + ((size_t)b * 64 + ocA) * HW + row * W + px) = vA;
                *(float2*)(out + ((size_t)b * 64 + ocB) * HW + row * W + px) = vB;
            }
        }
    }
}

// ---------------------------------------------------------------------------
// Offset/mask head (fp32 FFMA2, known good).
// ---------------------------------------------------------------------------
__global__ __launch_bounds__(128, 8)
void conv_offset_kernel(const float* __restrict__ in, const float* __restrict__ w,
                        const float* __restrict__ bias,
                        float* __restrict__ off_out, float* __restrict__ mask_out)
{
    constexpr int CI = 64;
    __shared__ float sw[CI * 9 * 10];
    const int t   = threadIdx.x;
    const int cog = blockIdx.y;
    const int b   = blockIdx.z;

    const float* wsrc = w + (size_t)cog * 9 * CI * 9;
    for (int i = t; i < 9 * CI * 9; i += 128) {
        const int o = i / (CI * 9);
        const int rest = i - o * (CI * 9);
        sw[rest * 10 + o] = wsrc[o * (CI * 9) + rest];
    }
    __syncthreads();

    const int tx = t & 63, ty = t >> 6;
    const int y  = blockIdx.x * 2 + ty;
    const int x0 = tx * 2;

    u64 accp[4][2];
    float accs[2];
#pragma unroll
    for (int pr = 0; pr < 4; pr++) { accp[pr][0] = 0ULL; accp[pr][1] = 0ULL; }
    accs[0] = accs[1] = 0.f;

    const bool vt = (y > 0), vb = (y < H - 1), vl = (x0 > 0), vr = (x0 + 2 < W);

    for (int ci = 0; ci < CI; ci++) {
        const float* p = in + ((size_t)b * CI + ci) * HW;
        float r[3][4];
        {
            const float* rp = p + y * W;
            float2 v = *(const float2*)(rp + x0);
            r[1][1] = v.x; r[1][2] = v.y;
            r[1][0] = vl ? rp[x0 - 1] : 0.f;
            r[1][3] = vr ? rp[x0 + 2] : 0.f;
        }
        {
            const float* rp = p + (y - 1) * W;
            float2 v = vt ? *(const float2*)(rp + x0) : make_float2(0.f, 0.f);
            r[0][1] = v.x; r[0][2] = v.y;
            r[0][0] = (vt && vl) ? rp[x0 - 1] : 0.f;
            r[0][3] = (vt && vr) ? rp[x0 + 2] : 0.f;
        }
        {
            const float* rp = p + (y + 1) * W;
            float2 v = vb ? *(const float2*)(rp + x0) : make_float2(0.f, 0.f);
            r[2][1] = v.x; r[2][2] = v.y;
            r[2][0] = (vb && vl) ? rp[x0 - 1] : 0.f;
            r[2][3] = (vb && vr) ? rp[x0 + 2] : 0.f;
        }

        const float* wci = sw + ci * 90;
#pragma unroll
        for (int dy = 0; dy < 3; dy++) {
            u64 xp[4];
#pragma unroll
            for (int j = 0; j < 4; j++) xp[j] = dup2(r[dy][j]);
#pragma unroll
            for (int dx = 0; dx < 3; dx++) {
                const int tap = dy * 3 + dx;
                const u64* wp = (const u64*)(wci + tap * 10);
                u64 wv[4];
#pragma unroll
                for (int pr = 0; pr < 4; pr++) wv[pr] = wp[pr];
                const float ws = wci[tap * 10 + 8];
#pragma unroll
                for (int px = 0; px < 2; px++) {
#pragma unroll
                    for (int pr = 0; pr < 4; pr++)
                        ffma2(accp[pr][px], xp[px + dx], wv[pr]);
                    accs[px] = fmaf(r[dy][px + dx], ws, accs[px]);
                }
            }
        }
    }

    const bool is_off = (cog < 2);
    float vals[9][2];
#pragma unroll
    for (int pr = 0; pr < 4; pr++) {
        const int co = cog * 9 + 2 * pr;
        const float b0 = bias[co], b1 = bias[co + 1];
#pragma unroll
        for (int px = 0; px < 2; px++) {
            float2 u = unpack2(accp[pr][px]);
            vals[2 * pr][px]     = u.x + b0;
            vals[2 * pr + 1][px] = u.y + b1;
        }
    }
    {
        const float bb = bias[cog * 9 + 8];
        vals[8][0] = accs[0] + bb;
        vals[8][1] = accs[1] + bb;
    }

#pragma unroll
    for (int o = 0; o < 9; o++) {
        const int co = cog * 9 + o;
        float2 v;
        if (is_off) {
            v.x = 15.f * tanhf(vals[o][0]);
            v.y = 15.f * tanhf(vals[o][1]);
            *(float2*)(off_out + ((size_t)b * 18 + co) * HW + y * W + x0) = v;
        } else {
            v.x = 1.f / (1.f + expf(-vals[o][0]));
            v.y = 1.f / (1.f + expf(-vals[o][1]));
            *(float2*)(mask_out + ((size_t)b * 9 + (co - 18)) * HW + y * W + x0) = v;
        }
    }
}

// ---------------------------------------------------------------------------
// DCNv2 + leaky ReLU, HMMA GEMM (bf16 3-term split on samples & weights).
// Block: 256 thr, tile = 64 px of one row x 64 oc. Grid: (2, H, B).
// Phase A (fp32): tap descriptors -> smem. Per k-chunk (9 x 64):
//   gather+combine S in fp32, write bf16 hi/lo to B planes [px][l pad74];
//   stage weight A chunk [var][oc][72]; then 4 x k16 MMA steps, 12 MMA each.
// smem: sIdx 9216 | sWt 9216 | Bh 9472 | Bl 9472 | A 18432 = 55808 B.
// ---------------------------------------------------------------------------
constexpr int DB_OFF   = 18432;
constexpr int DB_PLANE = 64 * 74 * 2;              // 9472
constexpr int DA_OFF   = DB_OFF + 2 * DB_PLANE;    // 37376
constexpr int DSM_SIZE = DA_OFF + 18432;           // 55808

__global__ __launch_bounds__(256, 3)
void dcn_mma_kernel(const float* __restrict__ x, const float* __restrict__ offs,
                    const float* __restrict__ mask, const __nv_bfloat16* __restrict__ Ad,
                    const float* __restrict__ bias, float* __restrict__ out)
{
    extern __shared__ __align__(16) char smem[];
    int*   sIdx = (int*)smem;                        // [4][9][64]
    float* sWt  = (float*)(smem + 9216);             // [4][9][64]
    const unsigned sbase = smem_u32(smem);

    const int t    = threadIdx.x;
    const int wid  = t >> 5;
    const int lane = t & 31;
    const int x0   = blockIdx.x * 64;
    const int y    = blockIdx.y;
    const int b    = blockIdx.z;

    // Stage 0: tap descriptors (fp32, exact)
    for (int i = t; i < 64 * K; i += 256) {
        const int px = i & 63;
        const int k  = i >> 6;
        const int xx = x0 + px;
        const int base = y * W + xx;
        const float oy = offs[((size_t)b * 18 + 2 * k) * HW + base];
        const float ox = offs[((size_t)b * 18 + 2 * k + 1) * HW + base];
        const float m  = mask[((size_t)b * K + k) * HW + base];
        const float py  = (float)(y + k / 3 - 1) + oy;
        const float pxx = (float)(xx + k % 3 - 1) + ox;
        const float fy = floorf(py), fx = floorf(pxx);
        const float wy = py - fy,  wx = pxx - fx;
        const int iy0 = (int)fy, ix0 = (int)fx;
#pragma unroll
        for (int c2 = 0; c2 < 4; c2++) {
            const int yy = iy0 + (c2 >> 1);
            const int xc = ix0 + (c2 & 1);
            const bool v = (yy >= 0) && (yy < H) && (xc >= 0) && (xc < W);
            const float wgt = ((c2 >> 1) ? wy : 1.f - wy) * ((c2 & 1) ? wx : 1.f - wx) * m;
            sIdx[(c2 * K + k) * 64 + px] = v ? (yy * W + xc) : 0;
            sWt [(c2 * K + k) * 64 + px] = v ? wgt : 0.f;
        }
    }
    __syncthreads();

    const int ocg = wid & 1;
    const int pxg = wid >> 1;
    float acc[2][2][4];                              // [mt][nt][4]
#pragma unroll
    for (int mt = 0; mt < 2; mt++)
#pragma unroll
        for (int nt = 0; nt < 2; nt++)
#pragma unroll
            for (int c = 0; c < 4; c++) acc[mt][nt][c] = 0.f;

    const float* xb = x + (size_t)b * NF * HW;

    for (int ch = 0; ch < 9; ch++) {
        if (ch) __syncthreads();
        // stage A weight chunk (18432 B contiguous)
        {
            const uint4* srcw = (const uint4*)((const char*)Ad + (size_t)ch * 18432);
            uint4* dst = (uint4*)(smem + DA_OFF);
            for (int i = t; i < 1152; i += 256) dst[i] = srcw[i];
        }
        // gather + combine -> B bf16 hi/lo planes [px][l pad74]
        for (int i = t; i < 64 * 64; i += 256) {
            const int px = i & 63;
            const int ll = i >> 6;
            const int lg = ch * 64 + ll;
            const int c  = lg / 9, k = lg - c * 9;
            const float* xp = xb + (size_t)c * HW;
            float s = 0.f;
#pragma unroll
            for (int c2 = 0; c2 < 4; c2++)
                s = fmaf(sWt[(c2 * K + k) * 64 + px],
                         __ldg(xp + sIdx[(c2 * K + k) * 64 + px]), s);
            const __nv_bfloat16 h = __float2bfloat16(s);
            const __nv_bfloat16 l = __float2bfloat16(s - __bfloat162float(h));
            const int eo = (px * 74 + ll) * 2;
            *(__nv_bfloat16*)(smem + DB_OFF + eo)            = h;
            *(__nv_bfloat16*)(smem + DB_OFF + DB_PLANE + eo) = l;
        }
        __syncthreads();

#pragma unroll 1
        for (int ks = 0; ks < 4; ks++) {
            unsigned Ah[2][4], Al[2][4];
#pragma unroll
            for (int mt = 0; mt < 2; mt++) {
                const unsigned ao = DA_OFF +
                    ((ocg * 32 + mt * 16 + (lane & 15)) * 72 + ks * 16 + (lane >> 4) * 8) * 2;
                ldsm4(Ah[mt], sbase + ao);
                ldsm4(Al[mt], sbase + ao + 9216);
            }
#pragma unroll
            for (int nt = 0; nt < 2; nt++) {
                const int pxn  = pxg * 16 + nt * 8 + (lane >> 2);
                const int koff = ks * 16 + 2 * (lane & 3);
                const int eo   = (pxn * 74 + koff) * 2;
                const unsigned bh0 = *(const unsigned*)(smem + DB_OFF + eo);
                const unsigned bh1 = *(const unsigned*)(smem + DB_OFF + eo + 16);
                const unsigned bl0 = *(const unsigned*)(smem + DB_OFF + DB_PLANE + eo);
                const unsigned bl1 = *(const unsigned*)(smem + DB_OFF + DB_PLANE + eo + 16);
#pragma unroll
                for (int mt = 0; mt < 2; mt++) {
                    mma16816(acc[mt][nt], Ah[mt], bh0, bh1);
                    mma16816(acc[mt][nt], Ah[mt], bl0, bl1);
                    mma16816(acc[mt][nt], Al[mt], bh0, bh1);
                }
            }
        }
    }

    // epilogue
#pragma unroll
    for (int mt = 0; mt < 2; mt++) {
        const int ocA = ocg * 32 + mt * 16 + (lane >> 2);
        const int ocB = ocA + 8;
        const float bA = __ldg(bias + ocA);
        const float bB = __ldg(bias + ocB);
#pragma unroll
        for (int nt = 0; nt < 2; nt++) {
            const int px = x0 + pxg * 16 + nt * 8 + 2 * (lane & 3);
            const float* c = acc[mt][nt];
            float2 vA, vB;
            vA.x = lrelu(c[0] + bA); vA.y = lrelu(c[1] + bA);
            vB.x = lrelu(c[2] + bB); vB.y = lrelu(c[3] + bB);
            *(float2*)(out + ((size_t)b * NF + ocA) * HW + y * W + px) = vA;
            *(float2*)(out + ((size_t)b * NF + ocB) * HW + y * W + px) = vB;
        }
    }
}

// ---------------------------------------------------------------------------
extern "C" void kernel_launch(void* const* d_in, const int* in_sizes, int n_in,
                              void* d_out, int out_size)
{
    const float* nbr   = (const float*)d_in[0];
    const float* ref   = (const float*)d_in[1];
    const float* w1    = (const float*)d_in[2];
    const float* b1    = (const float*)d_in[3];
    const float* w2    = (const float*)d_in[4];
    const float* b2    = (const float*)d_in[5];
    const float* w3    = (const float*)d_in[6];
    const float* b3    = (const float*)d_in[7];
    const float* w_off = (const float*)d_in[8];
    const float* b_off = (const float*)d_in[9];
    const float* w_dcn = (const float*)d_in[10];
    const float* b_dcn = (const float*)d_in[11];

    float* out  = (float*)d_out;
    float* feat = out;                                   // [B,64,H,W]
    float* offs = out + (size_t)BN * NF * HW;            // [B,18,H,W]
    float* msk  = offs + (size_t)BN * 18 * HW;           // [B, 9,H,W]

    float *bufA, *bufB;
    __nv_bfloat16 *A1, *A2, *A3, *Ad;
    cudaGetSymbolAddress((void**)&bufA, g_bufA);
    cudaGetSymbolAddress((void**)&bufB, g_bufB);
    cudaGetSymbolAddress((void**)&A1,   g_A1);
    cudaGetSymbolAddress((void**)&A2,   g_A2);
    cudaGetSymbolAddress((void**)&A3,   g_A3);
    cudaGetSymbolAddress((void**)&Ad,   g_Ad);

    prep_mma_w<2><<<576, 256>>>(w1, A1);
    prep_mma_w<1><<<288, 256>>>(w2, A2);
    prep_mma_w<1><<<288, 256>>>(w3, A3);
    prep_dcn_w<<<288, 256>>>(w_dcn, Ad);

    cudaFuncSetAttribute(conv_mma_kernel<2, true>,
                         cudaFuncAttributeMaxDynamicSharedMemorySize, CSM_SIZE);
    cudaFuncSetAttribute(conv_mma_kernel<1, false>,
                         cudaFuncAttributeMaxDynamicSharedMemorySize, CSM_SIZE);
    cudaFuncSetAttribute(dcn_mma_kernel,
                         cudaFuncAttributeMaxDynamicSharedMemorySize, DSM_SIZE);

    conv_mma_kernel<2, true ><<<dim3(2, 64, 4), 256, CSM_SIZE>>>(nbr, ref, A1, b1, bufA);
    conv_mma_kernel<1, false><<<dim3(2, 64, 4), 256, CSM_SIZE>>>(bufA, bufA, A2, b2, bufB);
    conv_mma_kernel<1, false><<<dim3(2, 64, 4), 256, CSM_SIZE>>>(bufB, bufB, A3, b3, bufA);
    conv_offset_kernel<<<dim3(64, 3, 4), 128>>>(bufA, w_off, b_off, offs, msk);

    dcn_mma_kernel<<<dim3(2, 128, 4), 256, DSM_SIZE>>>(nbr, offs, msk, Ad, b_dcn, feat);
}

// round 8
// speedup vs baseline: 1.4128x; 1.0137x over previous
#include <cuda_runtime.h>
#include <cuda_bf16.h>
#include <math.h>

// Problem constants
constexpr int BN = 4;
constexpr int NF = 64;
constexpr int H  = 128;
constexpr int W  = 128;
constexpr int HW = H * W;
constexpr int K  = 9;

// Scratch (device globals: no runtime allocation allowed)
__device__ float g_bufA[BN * NF * HW];
__device__ float g_bufB[BN * NF * HW];
__device__ __nv_bfloat16 g_A1[2 * 9 * 2 * 64 * 72]; // conv1 mma weights (hi/lo, pad72)
__device__ __nv_bfloat16 g_A2[1 * 9 * 2 * 64 * 72];
__device__ __nv_bfloat16 g_A3[1 * 9 * 2 * 64 * 72];
__device__ __nv_bfloat16 g_Ao[9 * 2 * 32 * 72];     // offset-head weights [tap][var][m32][72]
__device__ __nv_bfloat16 g_Ad[9 * 2 * 64 * 72];     // DCN weights [ch=k][var][oc][c pad72]

__device__ __forceinline__ float lrelu(float v) { return v >= 0.f ? v : 0.1f * v; }

// ---- mma.sync helpers ------------------------------------------------------
__device__ __forceinline__ unsigned smem_u32(const void* p) {
    unsigned a;
    asm("{ .reg .u64 t; cvta.to.shared.u64 t, %1; cvt.u32.u64 %0, t; }" : "=r"(a) : "l"(p));
    return a;
}
__device__ __forceinline__ void ldsm4(unsigned* a, unsigned saddr) {
    asm volatile("ldmatrix.sync.aligned.m8n8.x4.shared.b16 {%0,%1,%2,%3}, [%4];"
                 : "=r"(a[0]), "=r"(a[1]), "=r"(a[2]), "=r"(a[3]) : "r"(saddr));
}
__device__ __forceinline__ void mma16816(float* c, const unsigned* a, unsigned b0, unsigned b1) {
    asm volatile(
        "mma.sync.aligned.m16n8k16.row.col.f32.bf16.bf16.f32 "
        "{%0,%1,%2,%3}, {%4,%5,%6,%7}, {%8,%9}, {%0,%1,%2,%3};"
        : "+f"(c[0]), "+f"(c[1]), "+f"(c[2]), "+f"(c[3])
        : "r"(a[0]), "r"(a[1]), "r"(a[2]), "r"(a[3]), "r"(b0), "r"(b1));
}

// ---------------------------------------------------------------------------
// Prep kernels
// ---------------------------------------------------------------------------
template <int CC>
__global__ void prep_mma_w(const float* __restrict__ w, __nv_bfloat16* __restrict__ A)
{
    constexpr int CI = CC * 64;
    const int i = blockIdx.x * 256 + threadIdx.x;
    if (i >= CC * 9 * 2 * 4096) return;
    const int k   = i & 63;
    const int m   = (i >> 6) & 63;
    const int bt  = i >> 12;
    const int var = bt & 1;
    const int ct  = bt >> 1;            // cc*9 + tap
    const int tap = ct % 9;
    const int cc  = ct / 9;
    const float wv = w[((size_t)m * CI + cc * 64 + k) * 9 + tap];
    const __nv_bfloat16 h = __float2bfloat16(wv);
    const __nv_bfloat16 val = var ? __float2bfloat16(wv - __bfloat162float(h)) : h;
    A[(size_t)ct * 9216 + var * 4608 + m * 72 + k] = val;
}

// offset head: A[tap][var][m32][72], m<27 real, else 0
__global__ void prep_off_w(const float* __restrict__ w, __nv_bfloat16* __restrict__ A)
{
    const int i = blockIdx.x * 256 + threadIdx.x;
    if (i >= 9 * 2 * 32 * 64) return;
    const int k   = i & 63;
    const int m   = (i >> 6) & 31;
    const int var = (i >> 11) & 1;
    const int tap = i >> 12;
    float wv = 0.f;
    if (m < 27) wv = w[((size_t)m * 64 + k) * 9 + tap];
    const __nv_bfloat16 h = __float2bfloat16(wv);
    const __nv_bfloat16 val = var ? __float2bfloat16(wv - __bfloat162float(h)) : h;
    A[(size_t)(tap * 2 + var) * 2304 + m * 72 + k] = val;
}

// DCN k-major: A[ch][var][oc][c] = wd[oc][c][ch]
__global__ void prep_dcn_w(const float* __restrict__ wd, __nv_bfloat16* __restrict__ A)
{
    const int i = blockIdx.x * 256 + threadIdx.x;
    if (i >= 9 * 2 * 64 * 64) return;
    const int c   = i & 63;
    const int oc  = (i >> 6) & 63;
    const int var = (i >> 12) & 1;
    const int ch  = i >> 13;
    const float wv = wd[(size_t)oc * 576 + c * 9 + ch];
    const __nv_bfloat16 h = __float2bfloat16(wv);
    const __nv_bfloat16 val = var ? __float2bfloat16(wv - __bfloat162float(h)) : h;
    A[(size_t)ch * 9216 + var * 4608 + oc * 72 + c] = val;
}

// ---------------------------------------------------------------------------
// HMMA conv3x3 + bias + leaky ReLU, double-buffered A (1 sync/tap).
// Block 256 thr, tile 2 rows x 64 px x 64 oc. Grid (2, 64, B).
// ---------------------------------------------------------------------------
constexpr int BT_BYTES = 66 * 68 * 2;              // 8976 per row-plane
constexpr int A_OFF    = 8 * BT_BYTES;             // 71808
constexpr int CSM_SIZE = A_OFF + 2 * 18432;        // 108672

template <int CC, bool CONCAT>
__global__ __launch_bounds__(256, 2)
void conv_mma_kernel(const float* __restrict__ inA, const float* __restrict__ inB,
                     const __nv_bfloat16* __restrict__ Aw, const float* __restrict__ bias,
                     float* __restrict__ out)
{
    extern __shared__ __align__(16) char smem[];
    const unsigned sbase = smem_u32(smem);
    const int t    = threadIdx.x;
    const int wid  = t >> 5;
    const int lane = t & 31;
    const int x0   = blockIdx.x * 64;
    const int y0   = blockIdx.y * 2;
    const int b    = blockIdx.z;

    const int ocg = wid & 1;
    const int pxg = wid >> 1;

    float acc[2][2][2][4];
#pragma unroll
    for (int r = 0; r < 2; r++)
#pragma unroll
        for (int mt = 0; mt < 2; mt++)
#pragma unroll
            for (int nt = 0; nt < 2; nt++)
#pragma unroll
                for (int c = 0; c < 4; c++) acc[r][mt][nt][c] = 0.f;

    for (int cc = 0; cc < CC; cc++) {
        // ---- stage B: 4 rows x 64 ci x 66 px (halo), hi/lo bf16
        const float* src = CONCAT ? (cc ? inB : inA) : inA;
        for (int i = t; i < 4 * 64 * 66; i += 256) {
            const int pxi = i % 66;
            const int rci = i / 66;
            const int ci  = rci & 63;
            const int d   = rci >> 6;
            const int row = y0 + d - 1;
            const int xg  = x0 + pxi - 1;
            float v = 0.f;
            if (row >= 0 && row < H && xg >= 0 && xg < W)
                v = src[((size_t)b * 64 + ci) * HW + row * W + xg];
            const __nv_bfloat16 h = __float2bfloat16(v);
            const __nv_bfloat16 l = __float2bfloat16(v - __bfloat162float(h));
            const int eo = (pxi * 68 + ci) * 2;
            *(__nv_bfloat16*)(smem + (d * 2)     * BT_BYTES + eo) = h;
            *(__nv_bfloat16*)(smem + (d * 2 + 1) * BT_BYTES + eo) = l;
        }
        if (cc == 0) {
            // stage A for global tap 0 into buf0
            const uint4* srcw = (const uint4*)((const char*)Aw);
            uint4* dst = (uint4*)(smem + A_OFF);
            for (int i = t; i < 1152; i += 256) dst[i] = srcw[i];
        }
        __syncthreads();

        for (int tap = 0; tap < 9; tap++) {
            const int g = cc * 9 + tap;
            // prefetch next tap's A into the other buffer
            if (g + 1 < CC * 9) {
                const uint4* srcw = (const uint4*)((const char*)Aw + (size_t)(g + 1) * 18432);
                uint4* dst = (uint4*)(smem + A_OFF + ((g + 1) & 1) * 18432);
                for (int i = t; i < 1152; i += 256) dst[i] = srcw[i];
            }
            const unsigned abuf = A_OFF + (g & 1) * 18432;
            const int dy = tap / 3, dx = tap - dy * 3;
#pragma unroll 1
            for (int ks = 0; ks < 4; ks++) {
                unsigned Ah[2][4], Al[2][4];
#pragma unroll
                for (int mt = 0; mt < 2; mt++) {
                    const unsigned ao = abuf +
                        ((ocg * 32 + mt * 16 + (lane & 15)) * 72 + ks * 16 + (lane >> 4) * 8) * 2;
                    ldsm4(Ah[mt], sbase + ao);
                    ldsm4(Al[mt], sbase + ao + 9216);
                }
#pragma unroll
                for (int r = 0; r < 2; r++) {
                    const char* Bh = smem + ((r + dy) * 2)     * BT_BYTES;
                    const char* Bl = smem + ((r + dy) * 2 + 1) * BT_BYTES;
#pragma unroll
                    for (int nt = 0; nt < 2; nt++) {
                        const int pxi  = pxg * 16 + nt * 8 + (lane >> 2) + dx;
                        const int koff = ks * 16 + 2 * (lane & 3);
                        const int eo   = (pxi * 68 + koff) * 2;
                        const unsigned bh0 = *(const unsigned*)(Bh + eo);
                        const unsigned bh1 = *(const unsigned*)(Bh + eo + 16);
                        const unsigned bl0 = *(const unsigned*)(Bl + eo);
                        const unsigned bl1 = *(const unsigned*)(Bl + eo + 16);
#pragma unroll
                        for (int mt = 0; mt < 2; mt++) {
                            mma16816(acc[r][mt][nt], Ah[mt], bh0, bh1);
                            mma16816(acc[r][mt][nt], Ah[mt], bl0, bl1);
                            mma16816(acc[r][mt][nt], Al[mt], bh0, bh1);
                        }
                    }
                }
            }
            __syncthreads();
        }
    }

#pragma unroll
    for (int mt = 0; mt < 2; mt++) {
        const int ocA = ocg * 32 + mt * 16 + (lane >> 2);
        const int ocB = ocA + 8;
        const float bA = __ldg(bias + ocA);
        const float bB = __ldg(bias + ocB);
#pragma unroll
        for (int r = 0; r < 2; r++) {
            const int row = y0 + r;
#pragma unroll
            for (int nt = 0; nt < 2; nt++) {
                const int px = x0 + pxg * 16 + nt * 8 + 2 * (lane & 3);
                const float* c = acc[r][mt][nt];
                float2 vA, vB;
                vA.x = lrelu(c[0] + bA); vA.y = lrelu(c[1] + bA);
                vB.x = lrelu(c[2] + bB); vB.y = lrelu(c[3] + bB);
                *(float2*)(out + ((size_t)b * 64 + ocA) * HW + row * W + px) = vA;
                *(float2*)(out + ((size_t)b * 64 + ocB) * HW + row * W + px) = vB;
            }
        }
    }
}

// ---------------------------------------------------------------------------
// HMMA offset/mask head: conv 64 -> 27(pad 32), 15*tanh / sigmoid epilogue.
// Block 256 thr, tile 2 rows x 64 px x 32 oc. Grid (2, 64, B).
// Warps: r = wid&1 (row), pxg = wid>>1 (16-px group). A: 9216 B/tap, dbl-buf.
// ---------------------------------------------------------------------------
constexpr int OSM_SIZE = A_OFF + 2 * 9216;         // 90240

__global__ __launch_bounds__(256, 2)
void conv_off_mma_kernel(const float* __restrict__ in, const __nv_bfloat16* __restrict__ Aw,
                         const float* __restrict__ bias,
                         float* __restrict__ off_out, float* __restrict__ mask_out)
{
    extern __shared__ __align__(16) char smem[];
    const unsigned sbase = smem_u32(smem);
    const int t    = threadIdx.x;
    const int wid  = t >> 5;
    const int lane = t & 31;
    const int x0   = blockIdx.x * 64;
    const int y0   = blockIdx.y * 2;
    const int b    = blockIdx.z;

    const int r   = wid & 1;
    const int pxg = wid >> 1;

    float acc[2][2][4];                              // [mt][nt][4]
#pragma unroll
    for (int mt = 0; mt < 2; mt++)
#pragma unroll
        for (int nt = 0; nt < 2; nt++)
#pragma unroll
            for (int c = 0; c < 4; c++) acc[mt][nt][c] = 0.f;

    // stage B (4 rows x 64 ci x 66 px, hi/lo)
    for (int i = t; i < 4 * 64 * 66; i += 256) {
        const int pxi = i % 66;
        const int rci = i / 66;
        const int ci  = rci & 63;
        const int d   = rci >> 6;
        const int row = y0 + d - 1;
        const int xg  = x0 + pxi - 1;
        float v = 0.f;
        if (row >= 0 && row < H && xg >= 0 && xg < W)
            v = in[((size_t)b * 64 + ci) * HW + row * W + xg];
        const __nv_bfloat16 h = __float2bfloat16(v);
        const __nv_bfloat16 l = __float2bfloat16(v - __bfloat162float(h));
        const int eo = (pxi * 68 + ci) * 2;
        *(__nv_bfloat16*)(smem + (d * 2)     * BT_BYTES + eo) = h;
        *(__nv_bfloat16*)(smem + (d * 2 + 1) * BT_BYTES + eo) = l;
    }
    {   // stage A tap0
        const uint4* srcw = (const uint4*)((const char*)Aw);
        uint4* dst = (uint4*)(smem + A_OFF);
        for (int i = t; i < 576; i += 256) dst[i] = srcw[i];
    }
    __syncthreads();

    for (int tap = 0; tap < 9; tap++) {
        if (tap + 1 < 9) {
            const uint4* srcw = (const uint4*)((const char*)Aw + (size_t)(tap + 1) * 9216);
            uint4* dst = (uint4*)(smem + A_OFF + ((tap + 1) & 1) * 9216);
            for (int i = t; i < 576; i += 256) dst[i] = srcw[i];
        }
        const unsigned abuf = A_OFF + (tap & 1) * 9216;
        const int dy = tap / 3, dx = tap - dy * 3;
#pragma unroll 1
        for (int ks = 0; ks < 4; ks++) {
            unsigned Ah[2][4], Al[2][4];
#pragma unroll
            for (int mt = 0; mt < 2; mt++) {
                const unsigned ao = abuf +
                    ((mt * 16 + (lane & 15)) * 72 + ks * 16 + (lane >> 4) * 8) * 2;
                ldsm4(Ah[mt], sbase + ao);
                ldsm4(Al[mt], sbase + ao + 4608);
            }
            const char* Bh = smem + ((r + dy) * 2)     * BT_BYTES;
            const char* Bl = smem + ((r + dy) * 2 + 1) * BT_BYTES;
#pragma unroll
            for (int nt = 0; nt < 2; nt++) {
                const int pxi  = pxg * 16 + nt * 8 + (lane >> 2) + dx;
                const int koff = ks * 16 + 2 * (lane & 3);
                const int eo   = (pxi * 68 + koff) * 2;
                const unsigned bh0 = *(const unsigned*)(Bh + eo);
                const unsigned bh1 = *(const unsigned*)(Bh + eo + 16);
                const unsigned bl0 = *(const unsigned*)(Bl + eo);
                const unsigned bl1 = *(const unsigned*)(Bl + eo + 16);
#pragma unroll
                for (int mt = 0; mt < 2; mt++) {
                    mma16816(acc[mt][nt], Ah[mt], bh0, bh1);
                    mma16816(acc[mt][nt], Ah[mt], bl0, bl1);
                    mma16816(acc[mt][nt], Al[mt], bh0, bh1);
                }
            }
        }
        __syncthreads();
    }

    // epilogue: activations + split outputs
    const int row = y0 + r;
#pragma unroll
    for (int mt = 0; mt < 2; mt++) {
#pragma unroll
        for (int half = 0; half < 2; half++) {
            const int oc = mt * 16 + (lane >> 2) + half * 8;
            if (oc >= 27) continue;
            const float bb = __ldg(bias + oc);
#pragma unroll
            for (int nt = 0; nt < 2; nt++) {
                const int px = x0 + pxg * 16 + nt * 8 + 2 * (lane & 3);
                const float v0 = acc[mt][nt][2 * half]     + bb;
                const float v1 = acc[mt][nt][2 * half + 1] + bb;
                float2 v;
                if (oc < 18) {
                    v.x = 15.f * tanhf(v0);
                    v.y = 15.f * tanhf(v1);
                    *(float2*)(off_out + ((size_t)b * 18 + oc) * HW + row * W + px) = v;
                } else {
                    v.x = 1.f / (1.f + expf(-v0));
                    v.y = 1.f / (1.f + expf(-v1));
                    *(float2*)(mask_out + ((size_t)b * 9 + (oc - 18)) * HW + row * W + px) = v;
                }
            }
        }
    }
}

// ---------------------------------------------------------------------------
// DCNv2 + leaky ReLU, HMMA GEMM, k-major chunks (chunk ch == tap k).
// Block 256 thr, tile 64 px x 64 oc, K = 9 chunks x 64 c. Grid (2, H, B).
// Desc per (px,k): int4 corner indices + float4 mask-folded weights, loaded
// ONCE per chunk per thread into registers.
// smem: sIdx4 9216 | sW4 9216 | Bh 9472 | Bl 9472 | A 18432 = 55808.
// ---------------------------------------------------------------------------
constexpr int DW_OFF   = 9216;
constexpr int DB_OFF   = 18432;
constexpr int DB_PLANE = 64 * 74 * 2;              // 9472
constexpr int DA_OFF   = DB_OFF + 2 * DB_PLANE;    // 37376
constexpr int DSM_SIZE = DA_OFF + 18432;           // 55808

__global__ __launch_bounds__(256, 3)
void dcn_mma_kernel(const float* __restrict__ x, const float* __restrict__ offs,
                    const float* __restrict__ mask, const __nv_bfloat16* __restrict__ Ad,
                    const float* __restrict__ bias, float* __restrict__ out)
{
    extern __shared__ __align__(16) char smem[];
    int4*   sIdx4 = (int4*)smem;                     // [9][64]
    float4* sW4   = (float4*)(smem + DW_OFF);        // [9][64]
    const unsigned sbase = smem_u32(smem);

    const int t    = threadIdx.x;
    const int wid  = t >> 5;
    const int lane = t & 31;
    const int x0   = blockIdx.x * 64;
    const int y    = blockIdx.y;
    const int b    = blockIdx.z;

    // Stage 0: per-(px,k) descriptors (fp32, exact)
    for (int i = t; i < 64 * K; i += 256) {
        const int px = i & 63;
        const int k  = i >> 6;
        const int xx = x0 + px;
        const int base = y * W + xx;
        const float oy = offs[((size_t)b * 18 + 2 * k) * HW + base];
        const float ox = offs[((size_t)b * 18 + 2 * k + 1) * HW + base];
        const float m  = mask[((size_t)b * K + k) * HW + base];
        const float py  = (float)(y + k / 3 - 1) + oy;
        const float pxx = (float)(xx + k % 3 - 1) + ox;
        const float fy = floorf(py), fx = floorf(pxx);
        const float wy = py - fy,  wx = pxx - fx;
        const int iy0 = (int)fy, ix0 = (int)fx;
        const int iy1 = iy0 + 1, ix1 = ix0 + 1;
        const bool y0v = (iy0 >= 0) && (iy0 < H);
        const bool y1v = (iy1 >= 0) && (iy1 < H);
        const bool x0v = (ix0 >= 0) && (ix0 < W);
        const bool x1v = (ix1 >= 0) && (ix1 < W);
        const int y0c = min(max(iy0, 0), H - 1), y1c = min(max(iy1, 0), H - 1);
        const int x0c = min(max(ix0, 0), W - 1), x1c = min(max(ix1, 0), W - 1);
        int4 bi;
        bi.x = y0c * W + x0c; bi.y = y0c * W + x1c;
        bi.z = y1c * W + x0c; bi.w = y1c * W + x1c;
        float4 wv;
        wv.x = (y0v && x0v) ? (1.f - wy) * (1.f - wx) * m : 0.f;
        wv.y = (y0v && x1v) ? (1.f - wy) * wx * m         : 0.f;
        wv.z = (y1v && x0v) ? wy * (1.f - wx) * m         : 0.f;
        wv.w = (y1v && x1v) ? wy * wx * m                 : 0.f;
        sIdx4[k * 64 + px] = bi;
        sW4  [k * 64 + px] = wv;
    }
    __syncthreads();

    const int ocg = wid & 1;
    const int pxg = wid >> 1;
    float acc[2][2][4];
#pragma unroll
    for (int mt = 0; mt < 2; mt++)
#pragma unroll
        for (int nt = 0; nt < 2; nt++)
#pragma unroll
            for (int c = 0; c < 4; c++) acc[mt][nt][c] = 0.f;

    const float* xb = x + (size_t)b * NF * HW;
    const int gpx = t & 63;                          // gather px
    const int gcg = t >> 6;                          // gather c-group 0..3

    for (int ch = 0; ch < 9; ch++) {
        if (ch) __syncthreads();
        // stage A chunk
        {
            const uint4* srcw = (const uint4*)((const char*)Ad + (size_t)ch * 18432);
            uint4* dst = (uint4*)(smem + DA_OFF);
            for (int i = t; i < 1152; i += 256) dst[i] = srcw[i];
        }
        // gather: desc in regs, 16 s-values per thread (8 c-pairs)
        {
            const int4  bi = sIdx4[ch * 64 + gpx];
            const float4 wv = sW4 [ch * 64 + gpx];
            char* bh = smem + DB_OFF            + gpx * 148;   // 74*2
            char* bl = smem + DB_OFF + DB_PLANE + gpx * 148;
#pragma unroll
            for (int it = 0; it < 8; it++) {
                const int c0 = gcg * 16 + it * 2;
                const float* xp = xb + (size_t)c0 * HW;
                const float* xq = xp + HW;
                float s0 = wv.x * __ldg(xp + bi.x);
                s0 = fmaf(wv.y, __ldg(xp + bi.y), s0);
                s0 = fmaf(wv.z, __ldg(xp + bi.z), s0);
                s0 = fmaf(wv.w, __ldg(xp + bi.w), s0);
                float s1 = wv.x * __ldg(xq + bi.x);
                s1 = fmaf(wv.y, __ldg(xq + bi.y), s1);
                s1 = fmaf(wv.z, __ldg(xq + bi.z), s1);
                s1 = fmaf(wv.w, __ldg(xq + bi.w), s1);
                const __nv_bfloat16 h0 = __float2bfloat16(s0);
                const __nv_bfloat16 h1 = __float2bfloat16(s1);
                __nv_bfloat162 hp; hp.x = h0; hp.y = h1;
                __nv_bfloat162 lp;
                lp.x = __float2bfloat16(s0 - __bfloat162float(h0));
                lp.y = __float2bfloat16(s1 - __bfloat162float(h1));
                *(__nv_bfloat162*)(bh + c0 * 2) = hp;
                *(__nv_bfloat162*)(bl + c0 * 2) = lp;
            }
        }
        __syncthreads();

#pragma unroll 1
        for (int ks = 0; ks < 4; ks++) {
            unsigned Ah[2][4], Al[2][4];
#pragma unroll
            for (int mt = 0; mt < 2; mt++) {
                const unsigned ao = DA_OFF +
                    ((ocg * 32 + mt * 16 + (lane & 15)) * 72 + ks * 16 + (lane >> 4) * 8) * 2;
                ldsm4(Ah[mt], sbase + ao);
                ldsm4(Al[mt], sbase + ao + 9216);
            }
#pragma unroll
            for (int nt = 0; nt < 2; nt++) {
                const int pxn  = pxg * 16 + nt * 8 + (lane >> 2);
                const int koff = ks * 16 + 2 * (lane & 3);
                const int eo   = (pxn * 74 + koff) * 2;
                const unsigned bh0 = *(const unsigned*)(smem + DB_OFF + eo);
                const unsigned bh1 = *(const unsigned*)(smem + DB_OFF + eo + 16);
                const unsigned bl0 = *(const unsigned*)(smem + DB_OFF + DB_PLANE + eo);
                const unsigned bl1 = *(const unsigned*)(smem + DB_OFF + DB_PLANE + eo + 16);
#pragma unroll
                for (int mt = 0; mt < 2; mt++) {
                    mma16816(acc[mt][nt], Ah[mt], bh0, bh1);
                    mma16816(acc[mt][nt], Ah[mt], bl0, bl1);
                    mma16816(acc[mt][nt], Al[mt], bh0, bh1);
                }
            }
        }
    }

    // epilogue
#pragma unroll
    for (int mt = 0; mt < 2; mt++) {
        const int ocA = ocg * 32 + mt * 16 + (lane >> 2);
        const int ocB = ocA + 8;
        const float bA = __ldg(bias + ocA);
        const float bB = __ldg(bias + ocB);
#pragma unroll
        for (int nt = 0; nt < 2; nt++) {
            const int px = x0 + pxg * 16 + nt * 8 + 2 * (lane & 3);
            const float* c = acc[mt][nt];
            float2 vA, vB;
            vA.x = lrelu(c[0] + bA); vA.y = lrelu(c[1] + bA);
            vB.x = lrelu(c[2] + bB); vB.y = lrelu(c[3] + bB);
            *(float2*)(out + ((size_t)b * NF + ocA) * HW + y * W + px) = vA;
            *(float2*)(out + ((size_t)b * NF + ocB) * HW + y * W + px) = vB;
        }
    }
}

// ---------------------------------------------------------------------------
extern "C" void kernel_launch(void* const* d_in, const int* in_sizes, int n_in,
                              void* d_out, int out_size)
{
    const float* nbr   = (const float*)d_in[0];
    const float* ref   = (const float*)d_in[1];
    const float* w1    = (const float*)d_in[2];
    const float* b1    = (const float*)d_in[3];
    const float* w2    = (const float*)d_in[4];
    const float* b2    = (const float*)d_in[5];
    const float* w3    = (const float*)d_in[6];
    const float* b3    = (const float*)d_in[7];
    const float* w_off = (const float*)d_in[8];
    const float* b_off = (const float*)d_in[9];
    const float* w_dcn = (const float*)d_in[10];
    const float* b_dcn = (const float*)d_in[11];

    float* out  = (float*)d_out;
    float* feat = out;                                   // [B,64,H,W]
    float* offs = out + (size_t)BN * NF * HW;            // [B,18,H,W]
    float* msk  = offs + (size_t)BN * 18 * HW;           // [B, 9,H,W]

    float *bufA, *bufB;
    __nv_bfloat16 *A1, *A2, *A3, *Ao, *Ad;
    cudaGetSymbolAddress((void**)&bufA, g_bufA);
    cudaGetSymbolAddress((void**)&bufB, g_bufB);
    cudaGetSymbolAddress((void**)&A1,   g_A1);
    cudaGetSymbolAddress((void**)&A2,   g_A2);
    cudaGetSymbolAddress((void**)&A3,   g_A3);
    cudaGetSymbolAddress((void**)&Ao,   g_Ao);
    cudaGetSymbolAddress((void**)&Ad,   g_Ad);

    prep_mma_w<2><<<576, 256>>>(w1, A1);
    prep_mma_w<1><<<288, 256>>>(w2, A2);
    prep_mma_w<1><<<288, 256>>>(w3, A3);
    prep_off_w<<<144, 256>>>(w_off, Ao);
    prep_dcn_w<<<288, 256>>>(w_dcn, Ad);

    cudaFuncSetAttribute(conv_mma_kernel<2, true>,
                         cudaFuncAttributeMaxDynamicSharedMemorySize, CSM_SIZE);
    cudaFuncSetAttribute(conv_mma_kernel<1, false>,
                         cudaFuncAttributeMaxDynamicSharedMemorySize, CSM_SIZE);
    cudaFuncSetAttribute(conv_off_mma_kernel,
                         cudaFuncAttributeMaxDynamicSharedMemorySize, OSM_SIZE);
    cudaFuncSetAttribute(dcn_mma_kernel,
                         cudaFuncAttributeMaxDynamicSharedMemorySize, DSM_SIZE);

    conv_mma_kernel<2, true ><<<dim3(2, 64, 4), 256, CSM_SIZE>>>(nbr, ref, A1, b1, bufA);
    conv_mma_kernel<1, false><<<dim3(2, 64, 4), 256, CSM_SIZE>>>(bufA, bufA, A2, b2, bufB);
    conv_mma_kernel<1, false><<<dim3(2, 64, 4), 256, CSM_SIZE>>>(bufB, bufB, A3, b3, bufA);
    conv_off_mma_kernel<<<dim3(2, 64, 4), 256, OSM_SIZE>>>(bufA, Ao, b_off, offs, msk);

    dcn_mma_kernel<<<dim3(2, 128, 4), 256, DSM_SIZE>>>(nbr, offs, msk, Ad, b_dcn, feat);
}

// round 9
// speedup vs baseline: 1.4994x; 1.0613x over previous
#include <cuda_runtime.h>
#include <cuda_bf16.h>
#include <cuda_fp16.h>
#include <math.h>

// Problem constants
constexpr int BN = 4;
constexpr int NF = 64;
constexpr int H  = 128;
constexpr int W  = 128;
constexpr int HW = H * W;
constexpr int K  = 9;

// Scratch (device globals: no runtime allocation allowed)
__device__ unsigned g_bufA[BN * NF * HW];           // packed (bf16 hi | lo<<16)
__device__ unsigned g_bufB[BN * NF * HW];
__device__ __half   g_xh[BN * NF * HW];             // fp16 copy of nbr for DCN gather
__device__ __nv_bfloat16 g_A1[2 * 9 * 2 * 64 * 72]; // conv1 mma weights (hi/lo, pad72)
__device__ __nv_bfloat16 g_A2[1 * 9 * 2 * 64 * 72];
__device__ __nv_bfloat16 g_A3[1 * 9 * 2 * 64 * 72];
__device__ __nv_bfloat16 g_Ao[9 * 2 * 32 * 72];     // offset-head weights [tap][var][m32][72]
__device__ __nv_bfloat16 g_Ad[9 * 2 * 64 * 72];     // DCN weights [ch=k][var][oc][c pad72]

__device__ __forceinline__ float lrelu(float v) { return v >= 0.f ? v : 0.1f * v; }

__device__ __forceinline__ unsigned pack_hl(float v) {
    const __nv_bfloat16 h = __float2bfloat16(v);
    const __nv_bfloat16 l = __float2bfloat16(v - __bfloat162float(h));
    return (unsigned)__bfloat16_as_ushort(h) | ((unsigned)__bfloat16_as_ushort(l) << 16);
}

// ---- mma.sync helpers ------------------------------------------------------
__device__ __forceinline__ unsigned smem_u32(const void* p) {
    unsigned a;
    asm("{ .reg .u64 t; cvta.to.shared.u64 t, %1; cvt.u32.u64 %0, t; }" : "=r"(a) : "l"(p));
    return a;
}
__device__ __forceinline__ void ldsm4(unsigned* a, unsigned saddr) {
    asm volatile("ldmatrix.sync.aligned.m8n8.x4.shared.b16 {%0,%1,%2,%3}, [%4];"
                 : "=r"(a[0]), "=r"(a[1]), "=r"(a[2]), "=r"(a[3]) : "r"(saddr));
}
__device__ __forceinline__ void mma16816(float* c, const unsigned* a, unsigned b0, unsigned b1) {
    asm volatile(
        "mma.sync.aligned.m16n8k16.row.col.f32.bf16.bf16.f32 "
        "{%0,%1,%2,%3}, {%4,%5,%6,%7}, {%8,%9}, {%0,%1,%2,%3};"
        : "+f"(c[0]), "+f"(c[1]), "+f"(c[2]), "+f"(c[3])
        : "r"(a[0]), "r"(a[1]), "r"(a[2]), "r"(a[3]), "r"(b0), "r"(b1));
}

// ---------------------------------------------------------------------------
// Prep kernels
// ---------------------------------------------------------------------------
template <int CC>
__global__ void prep_mma_w(const float* __restrict__ w, __nv_bfloat16* __restrict__ A)
{
    constexpr int CI = CC * 64;
    const int i = blockIdx.x * 256 + threadIdx.x;
    if (i >= CC * 9 * 2 * 4096) return;
    const int k   = i & 63;
    const int m   = (i >> 6) & 63;
    const int bt  = i >> 12;
    const int var = bt & 1;
    const int ct  = bt >> 1;            // cc*9 + tap
    const int tap = ct % 9;
    const int cc  = ct / 9;
    const float wv = w[((size_t)m * CI + cc * 64 + k) * 9 + tap];
    const __nv_bfloat16 h = __float2bfloat16(wv);
    const __nv_bfloat16 val = var ? __float2bfloat16(wv - __bfloat162float(h)) : h;
    A[(size_t)ct * 9216 + var * 4608 + m * 72 + k] = val;
}

// offset head: A[tap][var][m32][72], m<27 real, else 0
__global__ void prep_off_w(const float* __restrict__ w, __nv_bfloat16* __restrict__ A)
{
    const int i = blockIdx.x * 256 + threadIdx.x;
    if (i >= 9 * 2 * 32 * 64) return;
    const int k   = i & 63;
    const int m   = (i >> 6) & 31;
    const int var = (i >> 11) & 1;
    const int tap = i >> 12;
    float wv = 0.f;
    if (m < 27) wv = w[((size_t)m * 64 + k) * 9 + tap];
    const __nv_bfloat16 h = __float2bfloat16(wv);
    const __nv_bfloat16 val = var ? __float2bfloat16(wv - __bfloat162float(h)) : h;
    A[(size_t)(tap * 2 + var) * 2304 + m * 72 + k] = val;
}

// DCN k-major: A[ch][var][oc][c] = wd[oc][c][ch]
__global__ void prep_dcn_w(const float* __restrict__ wd, __nv_bfloat16* __restrict__ A)
{
    const int i = blockIdx.x * 256 + threadIdx.x;
    if (i >= 9 * 2 * 64 * 64) return;
    const int c   = i & 63;
    const int oc  = (i >> 6) & 63;
    const int var = (i >> 12) & 1;
    const int ch  = i >> 13;
    const float wv = wd[(size_t)oc * 576 + c * 9 + ch];
    const __nv_bfloat16 h = __float2bfloat16(wv);
    const __nv_bfloat16 val = var ? __float2bfloat16(wv - __bfloat162float(h)) : h;
    A[(size_t)ch * 9216 + var * 4608 + oc * 72 + c] = val;
}

// fp16 copy of x for DCN gather
__global__ void prep_xh(const float* __restrict__ x, __half* __restrict__ xh)
{
    const int i = blockIdx.x * 256 + threadIdx.x;
    if (i < BN * NF * HW) xh[i] = __float2half(x[i]);
}

// ---------------------------------------------------------------------------
// HMMA conv3x3 + bias + leaky ReLU, double-buffered A (1 sync/tap).
// Block 256 thr, tile 2 rows x 64 px x 64 oc. Grid (2, 64, B).
// PACKED=false: fp32 concat inputs (conv1, CC=2). PACKED=true: packed hi/lo
// u32 input (conv2/3, CC=1). Output always packed hi/lo u32.
// ---------------------------------------------------------------------------
constexpr int BT_BYTES = 66 * 68 * 2;              // 8976 per row-plane
constexpr int A_OFF    = 8 * BT_BYTES;             // 71808
constexpr int CSM_SIZE = A_OFF + 2 * 18432;        // 108672

template <int CC, bool PACKED>
__global__ __launch_bounds__(256, 2)
void conv_mma_kernel(const float* __restrict__ fA, const float* __restrict__ fB,
                     const unsigned* __restrict__ pIn,
                     const __nv_bfloat16* __restrict__ Aw, const float* __restrict__ bias,
                     unsigned* __restrict__ out)
{
    extern __shared__ __align__(16) char smem[];
    const unsigned sbase = smem_u32(smem);
    const int t    = threadIdx.x;
    const int wid  = t >> 5;
    const int lane = t & 31;
    const int x0   = blockIdx.x * 64;
    const int y0   = blockIdx.y * 2;
    const int b    = blockIdx.z;

    const int ocg = wid & 1;
    const int pxg = wid >> 1;

    float acc[2][2][2][4];
#pragma unroll
    for (int r = 0; r < 2; r++)
#pragma unroll
        for (int mt = 0; mt < 2; mt++)
#pragma unroll
            for (int nt = 0; nt < 2; nt++)
#pragma unroll
                for (int c = 0; c < 4; c++) acc[r][mt][nt][c] = 0.f;

    for (int cc = 0; cc < CC; cc++) {
        // ---- stage B: 4 rows x 64 ci x 66 px (halo), hi/lo planes
        for (int i = t; i < 4 * 64 * 66; i += 256) {
            const int pxi = i % 66;
            const int rci = i / 66;
            const int ci  = rci & 63;
            const int d   = rci >> 6;
            const int row = y0 + d - 1;
            const int xg  = x0 + pxi - 1;
            const bool ok = (row >= 0 && row < H && xg >= 0 && xg < W);
            unsigned pv = 0;
            if (PACKED) {
                if (ok) pv = pIn[((size_t)b * 64 + ci) * HW + row * W + xg];
            } else {
                float v = 0.f;
                if (ok) {
                    const float* src = cc ? fB : fA;
                    v = src[((size_t)b * 64 + ci) * HW + row * W + xg];
                }
                pv = pack_hl(v);
            }
            const int eo = (pxi * 68 + ci) * 2;
            *(unsigned short*)(smem + (d * 2)     * BT_BYTES + eo) = (unsigned short)(pv & 0xFFFF);
            *(unsigned short*)(smem + (d * 2 + 1) * BT_BYTES + eo) = (unsigned short)(pv >> 16);
        }
        if (cc == 0) {
            const uint4* srcw = (const uint4*)((const char*)Aw);
            uint4* dst = (uint4*)(smem + A_OFF);
            for (int i = t; i < 1152; i += 256) dst[i] = srcw[i];
        }
        __syncthreads();

        for (int tap = 0; tap < 9; tap++) {
            const int g = cc * 9 + tap;
            if (g + 1 < CC * 9) {
                const uint4* srcw = (const uint4*)((const char*)Aw + (size_t)(g + 1) * 18432);
                uint4* dst = (uint4*)(smem + A_OFF + ((g + 1) & 1) * 18432);
                for (int i = t; i < 1152; i += 256) dst[i] = srcw[i];
            }
            const unsigned abuf = A_OFF + (g & 1) * 18432;
            const int dy = tap / 3, dx = tap - dy * 3;
#pragma unroll 1
            for (int ks = 0; ks < 4; ks++) {
                unsigned Ah[2][4], Al[2][4];
#pragma unroll
                for (int mt = 0; mt < 2; mt++) {
                    const unsigned ao = abuf +
                        ((ocg * 32 + mt * 16 + (lane & 15)) * 72 + ks * 16 + (lane >> 4) * 8) * 2;
                    ldsm4(Ah[mt], sbase + ao);
                    ldsm4(Al[mt], sbase + ao + 9216);
                }
#pragma unroll
                for (int r = 0; r < 2; r++) {
                    const char* Bh = smem + ((r + dy) * 2)     * BT_BYTES;
                    const char* Bl = smem + ((r + dy) * 2 + 1) * BT_BYTES;
#pragma unroll
                    for (int nt = 0; nt < 2; nt++) {
                        const int pxi  = pxg * 16 + nt * 8 + (lane >> 2) + dx;
                        const int koff = ks * 16 + 2 * (lane & 3);
                        const int eo   = (pxi * 68 + koff) * 2;
                        const unsigned bh0 = *(const unsigned*)(Bh + eo);
                        const unsigned bh1 = *(const unsigned*)(Bh + eo + 16);
                        const unsigned bl0 = *(const unsigned*)(Bl + eo);
                        const unsigned bl1 = *(const unsigned*)(Bl + eo + 16);
#pragma unroll
                        for (int mt = 0; mt < 2; mt++) {
                            mma16816(acc[r][mt][nt], Ah[mt], bh0, bh1);
                            mma16816(acc[r][mt][nt], Ah[mt], bl0, bl1);
                            mma16816(acc[r][mt][nt], Al[mt], bh0, bh1);
                        }
                    }
                }
            }
            __syncthreads();
        }
    }

#pragma unroll
    for (int mt = 0; mt < 2; mt++) {
        const int ocA = ocg * 32 + mt * 16 + (lane >> 2);
        const int ocB = ocA + 8;
        const float bA = __ldg(bias + ocA);
        const float bB = __ldg(bias + ocB);
#pragma unroll
        for (int r = 0; r < 2; r++) {
            const int row = y0 + r;
#pragma unroll
            for (int nt = 0; nt < 2; nt++) {
                const int px = x0 + pxg * 16 + nt * 8 + 2 * (lane & 3);
                const float* c = acc[r][mt][nt];
                uint2 pA, pB;
                pA.x = pack_hl(lrelu(c[0] + bA)); pA.y = pack_hl(lrelu(c[1] + bA));
                pB.x = pack_hl(lrelu(c[2] + bB)); pB.y = pack_hl(lrelu(c[3] + bB));
                *(uint2*)(out + ((size_t)b * 64 + ocA) * HW + row * W + px) = pA;
                *(uint2*)(out + ((size_t)b * 64 + ocB) * HW + row * W + px) = pB;
            }
        }
    }
}

// ---------------------------------------------------------------------------
// HMMA offset/mask head: conv 64 -> 27(pad 32), packed hi/lo input.
// Block 256 thr, tile 2 rows x 64 px x 32 oc. Grid (2, 64, B).
// ---------------------------------------------------------------------------
constexpr int OSM_SIZE = A_OFF + 2 * 9216;         // 90240

__global__ __launch_bounds__(256, 2)
void conv_off_mma_kernel(const unsigned* __restrict__ pIn, const __nv_bfloat16* __restrict__ Aw,
                         const float* __restrict__ bias,
                         float* __restrict__ off_out, float* __restrict__ mask_out)
{
    extern __shared__ __align__(16) char smem[];
    const unsigned sbase = smem_u32(smem);
    const int t    = threadIdx.x;
    const int wid  = t >> 5;
    const int lane = t & 31;
    const int x0   = blockIdx.x * 64;
    const int y0   = blockIdx.y * 2;
    const int b    = blockIdx.z;

    const int r   = wid & 1;
    const int pxg = wid >> 1;

    float acc[2][2][4];
#pragma unroll
    for (int mt = 0; mt < 2; mt++)
#pragma unroll
        for (int nt = 0; nt < 2; nt++)
#pragma unroll
            for (int c = 0; c < 4; c++) acc[mt][nt][c] = 0.f;

    for (int i = t; i < 4 * 64 * 66; i += 256) {
        const int pxi = i % 66;
        const int rci = i / 66;
        const int ci  = rci & 63;
        const int d   = rci >> 6;
        const int row = y0 + d - 1;
        const int xg  = x0 + pxi - 1;
        unsigned pv = 0;
        if (row >= 0 && row < H && xg >= 0 && xg < W)
            pv = pIn[((size_t)b * 64 + ci) * HW + row * W + xg];
        const int eo = (pxi * 68 + ci) * 2;
        *(unsigned short*)(smem + (d * 2)     * BT_BYTES + eo) = (unsigned short)(pv & 0xFFFF);
        *(unsigned short*)(smem + (d * 2 + 1) * BT_BYTES + eo) = (unsigned short)(pv >> 16);
    }
    {
        const uint4* srcw = (const uint4*)((const char*)Aw);
        uint4* dst = (uint4*)(smem + A_OFF);
        for (int i = t; i < 576; i += 256) dst[i] = srcw[i];
    }
    __syncthreads();

    for (int tap = 0; tap < 9; tap++) {
        if (tap + 1 < 9) {
            const uint4* srcw = (const uint4*)((const char*)Aw + (size_t)(tap + 1) * 9216);
            uint4* dst = (uint4*)(smem + A_OFF + ((tap + 1) & 1) * 9216);
            for (int i = t; i < 576; i += 256) dst[i] = srcw[i];
        }
        const unsigned abuf = A_OFF + (tap & 1) * 9216;
        const int dy = tap / 3, dx = tap - dy * 3;
#pragma unroll 1
        for (int ks = 0; ks < 4; ks++) {
            unsigned Ah[2][4], Al[2][4];
#pragma unroll
            for (int mt = 0; mt < 2; mt++) {
                const unsigned ao = abuf +
                    ((mt * 16 + (lane & 15)) * 72 + ks * 16 + (lane >> 4) * 8) * 2;
                ldsm4(Ah[mt], sbase + ao);
                ldsm4(Al[mt], sbase + ao + 4608);
            }
            const char* Bh = smem + ((r + dy) * 2)     * BT_BYTES;
            const char* Bl = smem + ((r + dy) * 2 + 1) * BT_BYTES;
#pragma unroll
            for (int nt = 0; nt < 2; nt++) {
                const int pxi  = pxg * 16 + nt * 8 + (lane >> 2) + dx;
                const int koff = ks * 16 + 2 * (lane & 3);
                const int eo   = (pxi * 68 + koff) * 2;
                const unsigned bh0 = *(const unsigned*)(Bh + eo);
                const unsigned bh1 = *(const unsigned*)(Bh + eo + 16);
                const unsigned bl0 = *(const unsigned*)(Bl + eo);
                const unsigned bl1 = *(const unsigned*)(Bl + eo + 16);
#pragma unroll
                for (int mt = 0; mt < 2; mt++) {
                    mma16816(acc[mt][nt], Ah[mt], bh0, bh1);
                    mma16816(acc[mt][nt], Ah[mt], bl0, bl1);
                    mma16816(acc[mt][nt], Al[mt], bh0, bh1);
                }
            }
        }
        __syncthreads();
    }

    const int row = y0 + r;
#pragma unroll
    for (int mt = 0; mt < 2; mt++) {
#pragma unroll
        for (int half = 0; half < 2; half++) {
            const int oc = mt * 16 + (lane >> 2) + half * 8;
            if (oc >= 27) continue;
            const float bb = __ldg(bias + oc);
#pragma unroll
            for (int nt = 0; nt < 2; nt++) {
                const int px = x0 + pxg * 16 + nt * 8 + 2 * (lane & 3);
                const float v0 = acc[mt][nt][2 * half]     + bb;
                const float v1 = acc[mt][nt][2 * half + 1] + bb;
                float2 v;
                if (oc < 18) {
                    v.x = 15.f * tanhf(v0);
                    v.y = 15.f * tanhf(v1);
                    *(float2*)(off_out + ((size_t)b * 18 + oc) * HW + row * W + px) = v;
                } else {
                    v.x = 1.f / (1.f + expf(-v0));
                    v.y = 1.f / (1.f + expf(-v1));
                    *(float2*)(mask_out + ((size_t)b * 9 + (oc - 18)) * HW + row * W + px) = v;
                }
            }
        }
    }
}

// ---------------------------------------------------------------------------
// DCNv2 + leaky ReLU, HMMA GEMM, k-major chunks, fp16 gather source.
// Block 256 thr, tile 64 px x 64 oc. Grid (2, H, B).
// ---------------------------------------------------------------------------
constexpr int DW_OFF   = 9216;
constexpr int DB_OFF   = 18432;
constexpr int DB_PLANE = 64 * 74 * 2;              // 9472
constexpr int DA_OFF   = DB_OFF + 2 * DB_PLANE;    // 37376
constexpr int DSM_SIZE = DA_OFF + 18432;           // 55808

__global__ __launch_bounds__(256, 3)
void dcn_mma_kernel(const __half* __restrict__ xh, const float* __restrict__ offs,
                    const float* __restrict__ mask, const __nv_bfloat16* __restrict__ Ad,
                    const float* __restrict__ bias, float* __restrict__ out)
{
    extern __shared__ __align__(16) char smem[];
    int4*   sIdx4 = (int4*)smem;                     // [9][64]
    float4* sW4   = (float4*)(smem + DW_OFF);        // [9][64]
    const unsigned sbase = smem_u32(smem);

    const int t    = threadIdx.x;
    const int wid  = t >> 5;
    const int lane = t & 31;
    const int x0   = blockIdx.x * 64;
    const int y    = blockIdx.y;
    const int b    = blockIdx.z;

    for (int i = t; i < 64 * K; i += 256) {
        const int px = i & 63;
        const int k  = i >> 6;
        const int xx = x0 + px;
        const int base = y * W + xx;
        const float oy = offs[((size_t)b * 18 + 2 * k) * HW + base];
        const float ox = offs[((size_t)b * 18 + 2 * k + 1) * HW + base];
        const float m  = mask[((size_t)b * K + k) * HW + base];
        const float py  = (float)(y + k / 3 - 1) + oy;
        const float pxx = (float)(xx + k % 3 - 1) + ox;
        const float fy = floorf(py), fx = floorf(pxx);
        const float wy = py - fy,  wx = pxx - fx;
        const int iy0 = (int)fy, ix0 = (int)fx;
        const int iy1 = iy0 + 1, ix1 = ix0 + 1;
        const bool y0v = (iy0 >= 0) && (iy0 < H);
        const bool y1v = (iy1 >= 0) && (iy1 < H);
        const bool x0v = (ix0 >= 0) && (ix0 < W);
        const bool x1v = (ix1 >= 0) && (ix1 < W);
        const int y0c = min(max(iy0, 0), H - 1), y1c = min(max(iy1, 0), H - 1);
        const int x0c = min(max(ix0, 0), W - 1), x1c = min(max(ix1, 0), W - 1);
        int4 bi;
        bi.x = y0c * W + x0c; bi.y = y0c * W + x1c;
        bi.z = y1c * W + x0c; bi.w = y1c * W + x1c;
        float4 wv;
        wv.x = (y0v && x0v) ? (1.f - wy) * (1.f - wx) * m : 0.f;
        wv.y = (y0v && x1v) ? (1.f - wy) * wx * m         : 0.f;
        wv.z = (y1v && x0v) ? wy * (1.f - wx) * m         : 0.f;
        wv.w = (y1v && x1v) ? wy * wx * m                 : 0.f;
        sIdx4[k * 64 + px] = bi;
        sW4  [k * 64 + px] = wv;
    }
    __syncthreads();

    const int ocg = wid & 1;
    const int pxg = wid >> 1;
    float acc[2][2][4];
#pragma unroll
    for (int mt = 0; mt < 2; mt++)
#pragma unroll
        for (int nt = 0; nt < 2; nt++)
#pragma unroll
            for (int c = 0; c < 4; c++) acc[mt][nt][c] = 0.f;

    const __half* xb = xh + (size_t)b * NF * HW;
    const int gpx = t & 63;
    const int gcg = t >> 6;

    for (int ch = 0; ch < 9; ch++) {
        if (ch) __syncthreads();
        {
            const uint4* srcw = (const uint4*)((const char*)Ad + (size_t)ch * 18432);
            uint4* dst = (uint4*)(smem + DA_OFF);
            for (int i = t; i < 1152; i += 256) dst[i] = srcw[i];
        }
        {
            const int4  bi = sIdx4[ch * 64 + gpx];
            const float4 wv = sW4 [ch * 64 + gpx];
            char* bh = smem + DB_OFF            + gpx * 148;
            char* bl = smem + DB_OFF + DB_PLANE + gpx * 148;
#pragma unroll
            for (int it = 0; it < 8; it++) {
                const int c0 = gcg * 16 + it * 2;
                const __half* xp = xb + (size_t)c0 * HW;
                const __half* xq = xp + HW;
                float s0 = wv.x * __half2float(__ldg(xp + bi.x));
                s0 = fmaf(wv.y, __half2float(__ldg(xp + bi.y)), s0);
                s0 = fmaf(wv.z, __half2float(__ldg(xp + bi.z)), s0);
                s0 = fmaf(wv.w, __half2float(__ldg(xp + bi.w)), s0);
                float s1 = wv.x * __half2float(__ldg(xq + bi.x));
                s1 = fmaf(wv.y, __half2float(__ldg(xq + bi.y)), s1);
                s1 = fmaf(wv.z, __half2float(__ldg(xq + bi.z)), s1);
                s1 = fmaf(wv.w, __half2float(__ldg(xq + bi.w)), s1);
                const __nv_bfloat16 h0 = __float2bfloat16(s0);
                const __nv_bfloat16 h1 = __float2bfloat16(s1);
                __nv_bfloat162 hp; hp.x = h0; hp.y = h1;
                __nv_bfloat162 lp;
                lp.x = __float2bfloat16(s0 - __bfloat162float(h0));
                lp.y = __float2bfloat16(s1 - __bfloat162float(h1));
                *(__nv_bfloat162*)(bh + c0 * 2) = hp;
                *(__nv_bfloat162*)(bl + c0 * 2) = lp;
            }
        }
        __syncthreads();

#pragma unroll 1
        for (int ks = 0; ks < 4; ks++) {
            unsigned Ah[2][4], Al[2][4];
#pragma unroll
            for (int mt = 0; mt < 2; mt++) {
                const unsigned ao = DA_OFF +
                    ((ocg * 32 + mt * 16 + (lane & 15)) * 72 + ks * 16 + (lane >> 4) * 8) * 2;
                ldsm4(Ah[mt], sbase + ao);
                ldsm4(Al[mt], sbase + ao + 9216);
            }
#pragma unroll
            for (int nt = 0; nt < 2; nt++) {
                const int pxn  = pxg * 16 + nt * 8 + (lane >> 2);
                const int koff = ks * 16 + 2 * (lane & 3);
                const int eo   = (pxn * 74 + koff) * 2;
                const unsigned bh0 = *(const unsigned*)(smem + DB_OFF + eo);
                const unsigned bh1 = *(const unsigned*)(smem + DB_OFF + eo + 16);
                const unsigned bl0 = *(const unsigned*)(smem + DB_OFF + DB_PLANE + eo);
                const unsigned bl1 = *(const unsigned*)(smem + DB_OFF + DB_PLANE + eo + 16);
#pragma unroll
                for (int mt = 0; mt < 2; mt++) {
                    mma16816(acc[mt][nt], Ah[mt], bh0, bh1);
                    mma16816(acc[mt][nt], Ah[mt], bl0, bl1);
                    mma16816(acc[mt][nt], Al[mt], bh0, bh1);
                }
            }
        }
    }

#pragma unroll
    for (int mt = 0; mt < 2; mt++) {
        const int ocA = ocg * 32 + mt * 16 + (lane >> 2);
        const int ocB = ocA + 8;
        const float bA = __ldg(bias + ocA);
        const float bB = __ldg(bias + ocB);
#pragma unroll
        for (int nt = 0; nt < 2; nt++) {
            const int px = x0 + pxg * 16 + nt * 8 + 2 * (lane & 3);
            const float* c = acc[mt][nt];
            float2 vA, vB;
            vA.x = lrelu(c[0] + bA); vA.y = lrelu(c[1] + bA);
            vB.x = lrelu(c[2] + bB); vB.y = lrelu(c[3] + bB);
            *(float2*)(out + ((size_t)b * NF + ocA) * HW + y * W + px) = vA;
            *(float2*)(out + ((size_t)b * NF + ocB) * HW + y * W + px) = vB;
        }
    }
}

// ---------------------------------------------------------------------------
extern "C" void kernel_launch(void* const* d_in, const int* in_sizes, int n_in,
                              void* d_out, int out_size)
{
    const float* nbr   = (const float*)d_in[0];
    const float* ref   = (const float*)d_in[1];
    const float* w1    = (const float*)d_in[2];
    const float* b1    = (const float*)d_in[3];
    const float* w2    = (const float*)d_in[4];
    const float* b2    = (const float*)d_in[5];
    const float* w3    = (const float*)d_in[6];
    const float* b3    = (const float*)d_in[7];
    const float* w_off = (const float*)d_in[8];
    const float* b_off = (const float*)d_in[9];
    const float* w_dcn = (const float*)d_in[10];
    const float* b_dcn = (const float*)d_in[11];

    float* out  = (float*)d_out;
    float* feat = out;                                   // [B,64,H,W]
    float* offs = out + (size_t)BN * NF * HW;            // [B,18,H,W]
    float* msk  = offs + (size_t)BN * 18 * HW;           // [B, 9,H,W]

    unsigned *bufA, *bufB;
    __half* xh;
    __nv_bfloat16 *A1, *A2, *A3, *Ao, *Ad;
    cudaGetSymbolAddress((void**)&bufA, g_bufA);
    cudaGetSymbolAddress((void**)&bufB, g_bufB);
    cudaGetSymbolAddress((void**)&xh,   g_xh);
    cudaGetSymbolAddress((void**)&A1,   g_A1);
    cudaGetSymbolAddress((void**)&A2,   g_A2);
    cudaGetSymbolAddress((void**)&A3,   g_A3);
    cudaGetSymbolAddress((void**)&Ao,   g_Ao);
    cudaGetSymbolAddress((void**)&Ad,   g_Ad);

    prep_mma_w<2><<<576, 256>>>(w1, A1);
    prep_mma_w<1><<<288, 256>>>(w2, A2);
    prep_mma_w<1><<<288, 256>>>(w3, A3);
    prep_off_w<<<144, 256>>>(w_off, Ao);
    prep_dcn_w<<<288, 256>>>(w_dcn, Ad);
    prep_xh<<<(BN * NF * HW + 255) / 256, 256>>>(nbr, xh);

    cudaFuncSetAttribute(conv_mma_kernel<2, false>,
                         cudaFuncAttributeMaxDynamicSharedMemorySize, CSM_SIZE);
    cudaFuncSetAttribute(conv_mma_kernel<1, true>,
                         cudaFuncAttributeMaxDynamicSharedMemorySize, CSM_SIZE);
    cudaFuncSetAttribute(conv_off_mma_kernel,
                         cudaFuncAttributeMaxDynamicSharedMemorySize, OSM_SIZE);
    cudaFuncSetAttribute(dcn_mma_kernel,
                         cudaFuncAttributeMaxDynamicSharedMemorySize, DSM_SIZE);

    conv_mma_kernel<2, false><<<dim3(2, 64, 4), 256, CSM_SIZE>>>(nbr, ref, nullptr, A1, b1, bufA);
    conv_mma_kernel<1, true ><<<dim3(2, 64, 4), 256, CSM_SIZE>>>(nullptr, nullptr, bufA, A2, b2, bufB);
    conv_mma_kernel<1, true ><<<dim3(2, 64, 4), 256, CSM_SIZE>>>(nullptr, nullptr, bufB, A3, b3, bufA);
    conv_off_mma_kernel<<<dim3(2, 64, 4), 256, OSM_SIZE>>>(bufA, Ao, b_off, offs, msk);

    dcn_mma_kernel<<<dim3(2, 128, 4), 256, DSM_SIZE>>>(xh, offs, msk, Ad, b_dcn, feat);
}

// round 11
// speedup vs baseline: 1.8099x; 1.2071x over previous
#include <cuda_runtime.h>
#include <cuda_bf16.h>
#include <cuda_fp16.h>
#include <math.h>

// Problem constants
constexpr int BN = 4;
constexpr int NF = 64;
constexpr int H  = 128;
constexpr int W  = 128;
constexpr int HW = H * W;
constexpr int K  = 9;

// Scratch (device globals: no runtime allocation allowed)
__device__ unsigned g_bufA[BN * NF * HW];           // packed (bf16 hi | lo<<16)
__device__ unsigned g_bufB[BN * NF * HW];
__device__ __align__(16) __half g_xt[BN * HW * NF]; // channel-last fp16 nbr for DCN gather
__device__ __nv_bfloat16 g_A1[2 * 9 * 2 * 64 * 72]; // conv1 mma weights (hi/lo, pad72)
__device__ __nv_bfloat16 g_A2[1 * 9 * 2 * 64 * 72];
__device__ __nv_bfloat16 g_A3[1 * 9 * 2 * 64 * 72];
__device__ __nv_bfloat16 g_Ao[9 * 2 * 32 * 72];     // offset-head weights [tap][var][m32][72]
__device__ __nv_bfloat16 g_Ad[9 * 2 * 64 * 72];     // DCN weights [ch=k][var][oc][c pad72]

__device__ __forceinline__ float lrelu(float v) { return v >= 0.f ? v : 0.1f * v; }

__device__ __forceinline__ unsigned pack_hl(float v) {
    const __nv_bfloat16 h = __float2bfloat16(v);
    const __nv_bfloat16 l = __float2bfloat16(v - __bfloat162float(h));
    return (unsigned)__bfloat16_as_ushort(h) | ((unsigned)__bfloat16_as_ushort(l) << 16);
}

// ---- mma.sync helpers ------------------------------------------------------
__device__ __forceinline__ unsigned smem_u32(const void* p) {
    unsigned a;
    asm("{ .reg .u64 t; cvta.to.shared.u64 t, %1; cvt.u32.u64 %0, t; }" : "=r"(a) : "l"(p));
    return a;
}
__device__ __forceinline__ void ldsm4(unsigned* a, unsigned saddr) {
    asm volatile("ldmatrix.sync.aligned.m8n8.x4.shared.b16 {%0,%1,%2,%3}, [%4];"
                 : "=r"(a[0]), "=r"(a[1]), "=r"(a[2]), "=r"(a[3]) : "r"(saddr));
}
__device__ __forceinline__ void mma16816(float* c, const unsigned* a, unsigned b0, unsigned b1) {
    asm volatile(
        "mma.sync.aligned.m16n8k16.row.col.f32.bf16.bf16.f32 "
        "{%0,%1,%2,%3}, {%4,%5,%6,%7}, {%8,%9}, {%0,%1,%2,%3};"
        : "+f"(c[0]), "+f"(c[1]), "+f"(c[2]), "+f"(c[3])
        : "r"(a[0]), "r"(a[1]), "r"(a[2]), "r"(a[3]), "r"(b0), "r"(b1));
}

// ---------------------------------------------------------------------------
// Merged weight prep: one launch handles A1, A2, A3, Ao, Ad (block-range dispatch).
// ---------------------------------------------------------------------------
__device__ __forceinline__ __nv_bfloat16 split_val(float wv, int var) {
    const __nv_bfloat16 h = __float2bfloat16(wv);
    return var ? __float2bfloat16(wv - __bfloat162float(h)) : h;
}

template <int CC>
__device__ __forceinline__ void prep_conv_w_elem(int i, const float* __restrict__ w,
                                                 __nv_bfloat16* __restrict__ A) {
    constexpr int CI = CC * 64;
    const int k   = i & 63;
    const int m   = (i >> 6) & 63;
    const int bt  = i >> 12;
    const int var = bt & 1;
    const int ct  = bt >> 1;            // cc*9 + tap
    const int tap = ct % 9;
    const int cc  = ct / 9;
    const float wv = w[((size_t)m * CI + cc * 64 + k) * 9 + tap];
    A[(size_t)ct * 9216 + var * 4608 + m * 72 + k] = split_val(wv, var);
}

__global__ void prep_weights(const float* __restrict__ w1, __nv_bfloat16* __restrict__ A1,
                             const float* __restrict__ w2, __nv_bfloat16* __restrict__ A2,
                             const float* __restrict__ w3, __nv_bfloat16* __restrict__ A3,
                             const float* __restrict__ wo, __nv_bfloat16* __restrict__ Ao,
                             const float* __restrict__ wd, __nv_bfloat16* __restrict__ Ad)
{
    const int blk = blockIdx.x;
    const int t   = threadIdx.x;
    if (blk < 576) {                                 // A1: 147456 elems
        prep_conv_w_elem<2>(blk * 256 + t, w1, A1);
    } else if (blk < 864) {                          // A2: 73728
        prep_conv_w_elem<1>((blk - 576) * 256 + t, w2, A2);
    } else if (blk < 1152) {                         // A3: 73728
        prep_conv_w_elem<1>((blk - 864) * 256 + t, w3, A3);
    } else if (blk < 1296) {                         // Ao: 36864
        const int i = (blk - 1152) * 256 + t;
        const int k   = i & 63;
        const int m   = (i >> 6) & 31;
        const int var = (i >> 11) & 1;
        const int tap = i >> 12;
        float wv = 0.f;
        if (m < 27) wv = wo[((size_t)m * 64 + k) * 9 + tap];
        Ao[(size_t)(tap * 2 + var) * 2304 + m * 72 + k] = split_val(wv, var);
    } else {                                         // Ad: 73728
        const int i = (blk - 1296) * 256 + t;
        const int c   = i & 63;
        const int oc  = (i >> 6) & 63;
        const int var = (i >> 12) & 1;
        const int ch  = i >> 13;
        const float wv = wd[(size_t)oc * 576 + c * 9 + ch];
        Ad[(size_t)ch * 9216 + var * 4608 + oc * 72 + c] = split_val(wv, var);
    }
}

// ---------------------------------------------------------------------------
// Channel-last fp16 transpose of nbr: xt[b][pos][c] = half(x[b][c][pos]).
// Block = 256 positions of one batch; smem tile 256 x 64 half, row pad 72
// (144 B -> 16-byte aligned rows for the uint4 read-out). Grid (64, B).
// ---------------------------------------------------------------------------
__global__ __launch_bounds__(256)
void prep_xt(const float* __restrict__ x, __half* __restrict__ xt)
{
    __shared__ __align__(16) __half tile[256 * 72];
    const int t    = threadIdx.x;
    const int pos0 = blockIdx.x * 256;
    const int b    = blockIdx.y;
    const float* xb = x + (size_t)b * NF * HW;
#pragma unroll 8
    for (int c = 0; c < 64; c++)
        tile[t * 72 + c] = __float2half(xb[(size_t)c * HW + pos0 + t]);
    __syncthreads();
    uint4* dst = (uint4*)(xt + ((size_t)b * HW + pos0) * 64);
    const uint4* srow = (const uint4*)(tile + t * 72);
#pragma unroll
    for (int j = 0; j < 8; j++) dst[t * 8 + j] = srow[j];
}

// ---------------------------------------------------------------------------
// HMMA conv3x3 + bias + leaky ReLU, double-buffered A (1 sync/tap).
// Block 256 thr, tile 2 rows x 64 px x 64 oc. Grid (2, 64, B).
// ---------------------------------------------------------------------------
constexpr int BT_BYTES = 66 * 68 * 2;              // 8976 per row-plane
constexpr int A_OFF    = 8 * BT_BYTES;             // 71808
constexpr int CSM_SIZE = A_OFF + 2 * 18432;        // 108672

template <int CC, bool PACKED>
__global__ __launch_bounds__(256, 2)
void conv_mma_kernel(const float* __restrict__ fA, const float* __restrict__ fB,
                     const unsigned* __restrict__ pIn,
                     const __nv_bfloat16* __restrict__ Aw, const float* __restrict__ bias,
                     unsigned* __restrict__ out)
{
    extern __shared__ __align__(16) char smem[];
    const unsigned sbase = smem_u32(smem);
    const int t    = threadIdx.x;
    const int wid  = t >> 5;
    const int lane = t & 31;
    const int x0   = blockIdx.x * 64;
    const int y0   = blockIdx.y * 2;
    const int b    = blockIdx.z;

    const int ocg = wid & 1;
    const int pxg = wid >> 1;

    float acc[2][2][2][4];
#pragma unroll
    for (int r = 0; r < 2; r++)
#pragma unroll
        for (int mt = 0; mt < 2; mt++)
#pragma unroll
            for (int nt = 0; nt < 2; nt++)
#pragma unroll
                for (int c = 0; c < 4; c++) acc[r][mt][nt][c] = 0.f;

    for (int cc = 0; cc < CC; cc++) {
        for (int i = t; i < 4 * 64 * 66; i += 256) {
            const int pxi = i % 66;
            const int rci = i / 66;
            const int ci  = rci & 63;
            const int d   = rci >> 6;
            const int row = y0 + d - 1;
            const int xg  = x0 + pxi - 1;
            const bool ok = (row >= 0 && row < H && xg >= 0 && xg < W);
            unsigned pv = 0;
            if (PACKED) {
                if (ok) pv = pIn[((size_t)b * 64 + ci) * HW + row * W + xg];
            } else {
                float v = 0.f;
                if (ok) {
                    const float* src = cc ? fB : fA;
                    v = src[((size_t)b * 64 + ci) * HW + row * W + xg];
                }
                pv = pack_hl(v);
            }
            const int eo = (pxi * 68 + ci) * 2;
            *(unsigned short*)(smem + (d * 2)     * BT_BYTES + eo) = (unsigned short)(pv & 0xFFFF);
            *(unsigned short*)(smem + (d * 2 + 1) * BT_BYTES + eo) = (unsigned short)(pv >> 16);
        }
        if (cc == 0) {
            const uint4* srcw = (const uint4*)((const char*)Aw);
            uint4* dst = (uint4*)(smem + A_OFF);
            for (int i = t; i < 1152; i += 256) dst[i] = srcw[i];
        }
        __syncthreads();

        for (int tap = 0; tap < 9; tap++) {
            const int g = cc * 9 + tap;
            if (g + 1 < CC * 9) {
                const uint4* srcw = (const uint4*)((const char*)Aw + (size_t)(g + 1) * 18432);
                uint4* dst = (uint4*)(smem + A_OFF + ((g + 1) & 1) * 18432);
                for (int i = t; i < 1152; i += 256) dst[i] = srcw[i];
            }
            const unsigned abuf = A_OFF + (g & 1) * 18432;
            const int dy = tap / 3, dx = tap - dy * 3;
#pragma unroll 1
            for (int ks = 0; ks < 4; ks++) {
                unsigned Ah[2][4], Al[2][4];
#pragma unroll
                for (int mt = 0; mt < 2; mt++) {
                    const unsigned ao = abuf +
                        ((ocg * 32 + mt * 16 + (lane & 15)) * 72 + ks * 16 + (lane >> 4) * 8) * 2;
                    ldsm4(Ah[mt], sbase + ao);
                    ldsm4(Al[mt], sbase + ao + 9216);
                }
#pragma unroll
                for (int r = 0; r < 2; r++) {
                    const char* Bh = smem + ((r + dy) * 2)     * BT_BYTES;
                    const char* Bl = smem + ((r + dy) * 2 + 1) * BT_BYTES;
#pragma unroll
                    for (int nt = 0; nt < 2; nt++) {
                        const int pxi  = pxg * 16 + nt * 8 + (lane >> 2) + dx;
                        const int koff = ks * 16 + 2 * (lane & 3);
                        const int eo   = (pxi * 68 + koff) * 2;
                        const unsigned bh0 = *(const unsigned*)(Bh + eo);
                        const unsigned bh1 = *(const unsigned*)(Bh + eo + 16);
                        const unsigned bl0 = *(const unsigned*)(Bl + eo);
                        const unsigned bl1 = *(const unsigned*)(Bl + eo + 16);
#pragma unroll
                        for (int mt = 0; mt < 2; mt++) {
                            mma16816(acc[r][mt][nt], Ah[mt], bh0, bh1);
                            mma16816(acc[r][mt][nt], Ah[mt], bl0, bl1);
                            mma16816(acc[r][mt][nt], Al[mt], bh0, bh1);
                        }
                    }
                }
            }
            __syncthreads();
        }
    }

#pragma unroll
    for (int mt = 0; mt < 2; mt++) {
        const int ocA = ocg * 32 + mt * 16 + (lane >> 2);
        const int ocB = ocA + 8;
        const float bA = __ldg(bias + ocA);
        const float bB = __ldg(bias + ocB);
#pragma unroll
        for (int r = 0; r < 2; r++) {
            const int row = y0 + r;
#pragma unroll
            for (int nt = 0; nt < 2; nt++) {
                const int px = x0 + pxg * 16 + nt * 8 + 2 * (lane & 3);
                const float* c = acc[r][mt][nt];
                uint2 pA, pB;
                pA.x = pack_hl(lrelu(c[0] + bA)); pA.y = pack_hl(lrelu(c[1] + bA));
                pB.x = pack_hl(lrelu(c[2] + bB)); pB.y = pack_hl(lrelu(c[3] + bB));
                *(uint2*)(out + ((size_t)b * 64 + ocA) * HW + row * W + px) = pA;
                *(uint2*)(out + ((size_t)b * 64 + ocB) * HW + row * W + px) = pB;
            }
        }
    }
}

// ---------------------------------------------------------------------------
// HMMA offset/mask head: conv 64 -> 27(pad 32), packed hi/lo input.
// ---------------------------------------------------------------------------
constexpr int OSM_SIZE = A_OFF + 2 * 9216;         // 90240

__global__ __launch_bounds__(256, 2)
void conv_off_mma_kernel(const unsigned* __restrict__ pIn, const __nv_bfloat16* __restrict__ Aw,
                         const float* __restrict__ bias,
                         float* __restrict__ off_out, float* __restrict__ mask_out)
{
    extern __shared__ __align__(16) char smem[];
    const unsigned sbase = smem_u32(smem);
    const int t    = threadIdx.x;
    const int wid  = t >> 5;
    const int lane = t & 31;
    const int x0   = blockIdx.x * 64;
    const int y0   = blockIdx.y * 2;
    const int b    = blockIdx.z;

    const int r   = wid & 1;
    const int pxg = wid >> 1;

    float acc[2][2][4];
#pragma unroll
    for (int mt = 0; mt < 2; mt++)
#pragma unroll
        for (int nt = 0; nt < 2; nt++)
#pragma unroll
            for (int c = 0; c < 4; c++) acc[mt][nt][c] = 0.f;

    for (int i = t; i < 4 * 64 * 66; i += 256) {
        const int pxi = i % 66;
        const int rci = i / 66;
        const int ci  = rci & 63;
        const int d   = rci >> 6;
        const int row = y0 + d - 1;
        const int xg  = x0 + pxi - 1;
        unsigned pv = 0;
        if (row >= 0 && row < H && xg >= 0 && xg < W)
            pv = pIn[((size_t)b * 64 + ci) * HW + row * W + xg];
        const int eo = (pxi * 68 + ci) * 2;
        *(unsigned short*)(smem + (d * 2)     * BT_BYTES + eo) = (unsigned short)(pv & 0xFFFF);
        *(unsigned short*)(smem + (d * 2 + 1) * BT_BYTES + eo) = (unsigned short)(pv >> 16);
    }
    {
        const uint4* srcw = (const uint4*)((const char*)Aw);
        uint4* dst = (uint4*)(smem + A_OFF);
        for (int i = t; i < 576; i += 256) dst[i] = srcw[i];
    }
    __syncthreads();

    for (int tap = 0; tap < 9; tap++) {
        if (tap + 1 < 9) {
            const uint4* srcw = (const uint4*)((const char*)Aw + (size_t)(tap + 1) * 9216);
            uint4* dst = (uint4*)(smem + A_OFF + ((tap + 1) & 1) * 9216);
            for (int i = t; i < 576; i += 256) dst[i] = srcw[i];
        }
        const unsigned abuf = A_OFF + (tap & 1) * 9216;
        const int dy = tap / 3, dx = tap - dy * 3;
#pragma unroll 1
        for (int ks = 0; ks < 4; ks++) {
            unsigned Ah[2][4], Al[2][4];
#pragma unroll
            for (int mt = 0; mt < 2; mt++) {
                const unsigned ao = abuf +
                    ((mt * 16 + (lane & 15)) * 72 + ks * 16 + (lane >> 4) * 8) * 2;
                ldsm4(Ah[mt], sbase + ao);
                ldsm4(Al[mt], sbase + ao + 4608);
            }
            const char* Bh = smem + ((r + dy) * 2)     * BT_BYTES;
            const char* Bl = smem + ((r + dy) * 2 + 1) * BT_BYTES;
#pragma unroll
            for (int nt = 0; nt < 2; nt++) {
                const int pxi  = pxg * 16 + nt * 8 + (lane >> 2) + dx;
                const int koff = ks * 16 + 2 * (lane & 3);
                const int eo   = (pxi * 68 + koff) * 2;
                const unsigned bh0 = *(const unsigned*)(Bh + eo);
                const unsigned bh1 = *(const unsigned*)(Bh + eo + 16);
                const unsigned bl0 = *(const unsigned*)(Bl + eo);
                const unsigned bl1 = *(const unsigned*)(Bl + eo + 16);
#pragma unroll
                for (int mt = 0; mt < 2; mt++) {
                    mma16816(acc[mt][nt], Ah[mt], bh0, bh1);
                    mma16816(acc[mt][nt], Ah[mt], bl0, bl1);
                    mma16816(acc[mt][nt], Al[mt], bh0, bh1);
                }
            }
        }
        __syncthreads();
    }

    const int row = y0 + r;
#pragma unroll
    for (int mt = 0; mt < 2; mt++) {
#pragma unroll
        for (int half = 0; half < 2; half++) {
            const int oc = mt * 16 + (lane >> 2) + half * 8;
            if (oc >= 27) continue;
            const float bb = __ldg(bias + oc);
#pragma unroll
            for (int nt = 0; nt < 2; nt++) {
                const int px = x0 + pxg * 16 + nt * 8 + 2 * (lane & 3);
                const float v0 = acc[mt][nt][2 * half]     + bb;
                const float v1 = acc[mt][nt][2 * half + 1] + bb;
                float2 v;
                if (oc < 18) {
                    v.x = 15.f * tanhf(v0);
                    v.y = 15.f * tanhf(v1);
                    *(float2*)(off_out + ((size_t)b * 18 + oc) * HW + row * W + px) = v;
                } else {
                    v.x = 1.f / (1.f + expf(-v0));
                    v.y = 1.f / (1.f + expf(-v1));
                    *(float2*)(mask_out + ((size_t)b * 9 + (oc - 18)) * HW + row * W + px) = v;
                }
            }
        }
    }
}

// ---------------------------------------------------------------------------
// DCNv2 + leaky ReLU, HMMA GEMM, k-major chunks, CHANNEL-LAST fp16 gather.
// Block 256 thr, tile 64 px x 64 oc. Grid (2, H, B).
// Gather: thread owns (px, 16-ch group); 4 corners x 2 LDG.128 each, half2 math.
// ---------------------------------------------------------------------------
constexpr int DW_OFF   = 9216;
constexpr int DB_OFF   = 18432;
constexpr int DB_PLANE = 64 * 74 * 2;              // 9472
constexpr int DA_OFF   = DB_OFF + 2 * DB_PLANE;    // 37376
constexpr int DSM_SIZE = DA_OFF + 18432;           // 55808

__global__ __launch_bounds__(256, 3)
void dcn_mma_kernel(const __half* __restrict__ xt, const float* __restrict__ offs,
                    const float* __restrict__ mask, const __nv_bfloat16* __restrict__ Ad,
                    const float* __restrict__ bias, float* __restrict__ out)
{
    extern __shared__ __align__(16) char smem[];
    int4*   sIdx4 = (int4*)smem;                     // [9][64]
    float4* sW4   = (float4*)(smem + DW_OFF);        // [9][64]
    const unsigned sbase = smem_u32(smem);

    const int t    = threadIdx.x;
    const int wid  = t >> 5;
    const int lane = t & 31;
    const int x0   = blockIdx.x * 64;
    const int y    = blockIdx.y;
    const int b    = blockIdx.z;

    for (int i = t; i < 64 * K; i += 256) {
        const int px = i & 63;
        const int k  = i >> 6;
        const int xx = x0 + px;
        const int base = y * W + xx;
        const float oy = offs[((size_t)b * 18 + 2 * k) * HW + base];
        const float ox = offs[((size_t)b * 18 + 2 * k + 1) * HW + base];
        const float m  = mask[((size_t)b * K + k) * HW + base];
        const float py  = (float)(y + k / 3 - 1) + oy;
        const float pxx = (float)(xx + k % 3 - 1) + ox;
        const float fy = floorf(py), fx = floorf(pxx);
        const float wy = py - fy,  wx = pxx - fx;
        const int iy0 = (int)fy, ix0 = (int)fx;
        const int iy1 = iy0 + 1, ix1 = ix0 + 1;
        const bool y0v = (iy0 >= 0) && (iy0 < H);
        const bool y1v = (iy1 >= 0) && (iy1 < H);
        const bool x0v = (ix0 >= 0) && (ix0 < W);
        const bool x1v = (ix1 >= 0) && (ix1 < W);
        const int y0c = min(max(iy0, 0), H - 1), y1c = min(max(iy1, 0), H - 1);
        const int x0c = min(max(ix0, 0), W - 1), x1c = min(max(ix1, 0), W - 1);
        int4 bi;
        bi.x = y0c * W + x0c; bi.y = y0c * W + x1c;
        bi.z = y1c * W + x0c; bi.w = y1c * W + x1c;
        float4 wv;
        wv.x = (y0v && x0v) ? (1.f - wy) * (1.f - wx) * m : 0.f;
        wv.y = (y0v && x1v) ? (1.f - wy) * wx * m         : 0.f;
        wv.z = (y1v && x0v) ? wy * (1.f - wx) * m         : 0.f;
        wv.w = (y1v && x1v) ? wy * wx * m                 : 0.f;
        sIdx4[k * 64 + px] = bi;
        sW4  [k * 64 + px] = wv;
    }
    __syncthreads();

    const int ocg = wid & 1;
    const int pxg = wid >> 1;
    float acc[2][2][4];
#pragma unroll
    for (int mt = 0; mt < 2; mt++)
#pragma unroll
        for (int nt = 0; nt < 2; nt++)
#pragma unroll
            for (int c = 0; c < 4; c++) acc[mt][nt][c] = 0.f;

    const __half* xbt = xt + (size_t)b * HW * 64;
    const int gpx = t & 63;                          // gather px
    const int gcg = t >> 6;                          // gather 16-ch group 0..3

    for (int ch = 0; ch < 9; ch++) {
        if (ch) __syncthreads();
        {
            const uint4* srcw = (const uint4*)((const char*)Ad + (size_t)ch * 18432);
            uint4* dst = (uint4*)(smem + DA_OFF);
            for (int i = t; i < 1152; i += 256) dst[i] = srcw[i];
        }
        // gather: channel-last, vectorized 16-ch runs per corner
        {
            const int4  bi = sIdx4[ch * 64 + gpx];
            const float4 wv = sW4 [ch * 64 + gpx];
            const uint4* p0 = (const uint4*)(xbt + (size_t)bi.x * 64 + gcg * 16);
            const uint4* p1 = (const uint4*)(xbt + (size_t)bi.y * 64 + gcg * 16);
            const uint4* p2 = (const uint4*)(xbt + (size_t)bi.z * 64 + gcg * 16);
            const uint4* p3 = (const uint4*)(xbt + (size_t)bi.w * 64 + gcg * 16);
            __align__(16) __half2 v0[8], v1[8], v2[8], v3[8];
            *(uint4*)(v0)     = __ldg(p0);  *(uint4*)(v0 + 4) = __ldg(p0 + 1);
            *(uint4*)(v1)     = __ldg(p1);  *(uint4*)(v1 + 4) = __ldg(p1 + 1);
            *(uint4*)(v2)     = __ldg(p2);  *(uint4*)(v2 + 4) = __ldg(p2 + 1);
            *(uint4*)(v3)     = __ldg(p3);  *(uint4*)(v3 + 4) = __ldg(p3 + 1);
            char* bh = smem + DB_OFF            + gpx * 148 + gcg * 32;
            char* bl = smem + DB_OFF + DB_PLANE + gpx * 148 + gcg * 32;
#pragma unroll
            for (int i = 0; i < 8; i++) {
                const float2 f0 = __half22float2(v0[i]);
                const float2 f1 = __half22float2(v1[i]);
                const float2 f2 = __half22float2(v2[i]);
                const float2 f3 = __half22float2(v3[i]);
                float s0 = wv.x * f0.x;
                s0 = fmaf(wv.y, f1.x, s0);
                s0 = fmaf(wv.z, f2.x, s0);
                s0 = fmaf(wv.w, f3.x, s0);
                float s1 = wv.x * f0.y;
                s1 = fmaf(wv.y, f1.y, s1);
                s1 = fmaf(wv.z, f2.y, s1);
                s1 = fmaf(wv.w, f3.y, s1);
                const __nv_bfloat16 h0 = __float2bfloat16(s0);
                const __nv_bfloat16 h1 = __float2bfloat16(s1);
                __nv_bfloat162 hp; hp.x = h0; hp.y = h1;
                __nv_bfloat162 lp;
                lp.x = __float2bfloat16(s0 - __bfloat162float(h0));
                lp.y = __float2bfloat16(s1 - __bfloat162float(h1));
                *(__nv_bfloat162*)(bh + i * 4) = hp;
                *(__nv_bfloat162*)(bl + i * 4) = lp;
            }
        }
        __syncthreads();

#pragma unroll 1
        for (int ks = 0; ks < 4; ks++) {
            unsigned Ah[2][4], Al[2][4];
#pragma unroll
            for (int mt = 0; mt < 2; mt++) {
                const unsigned ao = DA_OFF +
                    ((ocg * 32 + mt * 16 + (lane & 15)) * 72 + ks * 16 + (lane >> 4) * 8) * 2;
                ldsm4(Ah[mt], sbase + ao);
                ldsm4(Al[mt], sbase + ao + 9216);
            }
#pragma unroll
            for (int nt = 0; nt < 2; nt++) {
                const int pxn  = pxg * 16 + nt * 8 + (lane >> 2);
                const int koff = ks * 16 + 2 * (lane & 3);
                const int eo   = (pxn * 74 + koff) * 2;
                const unsigned bh0 = *(const unsigned*)(smem + DB_OFF + eo);
                const unsigned bh1 = *(const unsigned*)(smem + DB_OFF + eo + 16);
                const unsigned bl0 = *(const unsigned*)(smem + DB_OFF + DB_PLANE + eo);
                const unsigned bl1 = *(const unsigned*)(smem + DB_OFF + DB_PLANE + eo + 16);
#pragma unroll
                for (int mt = 0; mt < 2; mt++) {
                    mma16816(acc[mt][nt], Ah[mt], bh0, bh1);
                    mma16816(acc[mt][nt], Ah[mt], bl0, bl1);
                    mma16816(acc[mt][nt], Al[mt], bh0, bh1);
                }
            }
        }
    }

#pragma unroll
    for (int mt = 0; mt < 2; mt++) {
        const int ocA = ocg * 32 + mt * 16 + (lane >> 2);
        const int ocB = ocA + 8;
        const float bA = __ldg(bias + ocA);
        const float bB = __ldg(bias + ocB);
#pragma unroll
        for (int nt = 0; nt < 2; nt++) {
            const int px = x0 + pxg * 16 + nt * 8 + 2 * (lane & 3);
            const float* c = acc[mt][nt];
            float2 vA, vB;
            vA.x = lrelu(c[0] + bA); vA.y = lrelu(c[1] + bA);
            vB.x = lrelu(c[2] + bB); vB.y = lrelu(c[3] + bB);
            *(float2*)(out + ((size_t)b * NF + ocA) * HW + y * W + px) = vA;
            *(float2*)(out + ((size_t)b * NF + ocB) * HW + y * W + px) = vB;
        }
    }
}

// ---------------------------------------------------------------------------
extern "C" void kernel_launch(void* const* d_in, const int* in_sizes, int n_in,
                              void* d_out, int out_size)
{
    const float* nbr   = (const float*)d_in[0];
    const float* ref   = (const float*)d_in[1];
    const float* w1    = (const float*)d_in[2];
    const float* b1    = (const float*)d_in[3];
    const float* w2    = (const float*)d_in[4];
    const float* b2    = (const float*)d_in[5];
    const float* w3    = (const float*)d_in[6];
    const float* b3    = (const float*)d_in[7];
    const float* w_off = (const float*)d_in[8];
    const float* b_off = (const float*)d_in[9];
    const float* w_dcn = (const float*)d_in[10];
    const float* b_dcn = (const float*)d_in[11];

    float* out  = (float*)d_out;
    float* feat = out;                                   // [B,64,H,W]
    float* offs = out + (size_t)BN * NF * HW;            // [B,18,H,W]
    float* msk  = offs + (size_t)BN * 18 * HW;           // [B, 9,H,W]

    unsigned *bufA, *bufB;
    __half* xt;
    __nv_bfloat16 *A1, *A2, *A3, *Ao, *Ad;
    cudaGetSymbolAddress((void**)&bufA, g_bufA);
    cudaGetSymbolAddress((void**)&bufB, g_bufB);
    cudaGetSymbolAddress((void**)&xt,   g_xt);
    cudaGetSymbolAddress((void**)&A1,   g_A1);
    cudaGetSymbolAddress((void**)&A2,   g_A2);
    cudaGetSymbolAddress((void**)&A3,   g_A3);
    cudaGetSymbolAddress((void**)&Ao,   g_Ao);
    cudaGetSymbolAddress((void**)&Ad,   g_Ad);

    prep_weights<<<1584, 256>>>(w1, A1, w2, A2, w3, A3, w_off, Ao, w_dcn, Ad);
    prep_xt<<<dim3(64, BN), 256>>>(nbr, xt);

    cudaFuncSetAttribute(conv_mma_kernel<2, false>,
                         cudaFuncAttributeMaxDynamicSharedMemorySize, CSM_SIZE);
    cudaFuncSetAttribute(conv_mma_kernel<1, true>,
                         cudaFuncAttributeMaxDynamicSharedMemorySize, CSM_SIZE);
    cudaFuncSetAttribute(conv_off_mma_kernel,
                         cudaFuncAttributeMaxDynamicSharedMemorySize, OSM_SIZE);
    cudaFuncSetAttribute(dcn_mma_kernel,
                         cudaFuncAttributeMaxDynamicSharedMemorySize, DSM_SIZE);

    conv_mma_kernel<2, false><<<dim3(2, 64, 4), 256, CSM_SIZE>>>(nbr, ref, nullptr, A1, b1, bufA);
    conv_mma_kernel<1, true ><<<dim3(2, 64, 4), 256, CSM_SIZE>>>(nullptr, nullptr, bufA, A2, b2, bufB);
    conv_mma_kernel<1, true ><<<dim3(2, 64, 4), 256, CSM_SIZE>>>(nullptr, nullptr, bufB, A3, b3, bufA);
    conv_off_mma_kernel<<<dim3(2, 64, 4), 256, OSM_SIZE>>>(bufA, Ao, b_off, offs, msk);

    dcn_mma_kernel<<<dim3(2, 128, 4), 256, DSM_SIZE>>>(xt, offs, msk, Ad, b_dcn, feat);
}